// round 1
// baseline (speedup 1.0000x reference)
#include <cuda_runtime.h>

// Problem constants
#define HH    96
#define WWID  96
#define HWSZ  (HH * WWID)      // 9216
#define BATCH 8
#define CIN   256
#define ACH   128              // attn channels
#define KWIN  7
#define NOFF  (KWIN * KWIN)    // 49
#define NPIX  (BATCH * HWSZ)   // 73728

// Scratch for q and k in pixel-major [pixel][channel] layout (channel contiguous)
__device__ float g_q[(size_t)NPIX * ACH];
__device__ float g_k[(size_t)NPIX * ACH];

// ---------------------------------------------------------------------------
// Kernel 1: QK 1x1-conv GEMM.
// out[row][pixel] = sum_c W[row][c] * x[b][c][hw]
// blockIdx.y == 0 -> w_q -> g_q ; == 1 -> w_k -> g_k
// Tile: BM=128 rows x BN=64 pixels, BK=16, 256 threads, 8x4 microtile.
// ---------------------------------------------------------------------------
#define BM 128
#define BN 64
#define BK 16

__global__ __launch_bounds__(256) void qk_gemm_kernel(
    const float* __restrict__ x,
    const float* __restrict__ w_q,
    const float* __restrict__ w_k)
{
    const int nb = blockIdx.x;          // pixel block
    const int mb = blockIdx.y;          // 0=q, 1=k
    const float* __restrict__ W = mb ? w_k : w_q;
    float* __restrict__ out = mb ? g_k : g_q;

    const int n0  = nb * BN;            // global pixel base (flat over B*H*W)
    const int b   = n0 / HWSZ;
    const int hw0 = n0 % HWSZ;          // BN=64 divides HWSZ=9216 -> no batch crossing
    const float* __restrict__ xb = x + (size_t)b * CIN * HWSZ + hw0;

    __shared__ float As[BM][BK + 1];    // [row][c], +1 pad
    __shared__ float Bs[BK][BN];        // [c][pixel]

    const int tid = threadIdx.x;
    const int tx  = tid & 15;           // pixel group: pixels tx*4 .. tx*4+3
    const int ty  = tid >> 4;           // row group:   rows   ty*8 .. ty*8+7

    float acc[8][4];
#pragma unroll
    for (int r = 0; r < 8; r++)
#pragma unroll
        for (int j = 0; j < 4; j++) acc[r][j] = 0.0f;

    for (int kt = 0; kt < CIN; kt += BK) {
        // Load A tile: 128 rows x 16 c = 512 float4, 2 per thread
#pragma unroll
        for (int i = 0; i < 2; i++) {
            int f4 = tid + i * 256;
            int row = f4 >> 2;
            int c4  = (f4 & 3) * 4;
            float4 v = *(const float4*)&W[(size_t)row * CIN + kt + c4];
            As[row][c4 + 0] = v.x;
            As[row][c4 + 1] = v.y;
            As[row][c4 + 2] = v.z;
            As[row][c4 + 3] = v.w;
        }
        // Load B tile: 16 c x 64 px = 256 float4, 1 per thread
        {
            int c  = tid >> 4;
            int p4 = (tid & 15) * 4;
            float4 v = *(const float4*)&xb[(size_t)(kt + c) * HWSZ + p4];
            *(float4*)&Bs[c][p4] = v;
        }
        __syncthreads();

#pragma unroll
        for (int c = 0; c < BK; c++) {
            float a_[8];
#pragma unroll
            for (int r = 0; r < 8; r++) a_[r] = As[ty * 8 + r][c];
            float4 bv = *(const float4*)&Bs[c][tx * 4];
            float b_[4] = {bv.x, bv.y, bv.z, bv.w};
#pragma unroll
            for (int r = 0; r < 8; r++)
#pragma unroll
                for (int j = 0; j < 4; j++)
                    acc[r][j] = fmaf(a_[r], b_[j], acc[r][j]);
        }
        __syncthreads();
    }

    // Write out: pixel-major [pixel][128]
#pragma unroll
    for (int j = 0; j < 4; j++) {
        size_t base = (size_t)(n0 + tx * 4 + j) * ACH + ty * 8;
        float4 v0 = make_float4(acc[0][j], acc[1][j], acc[2][j], acc[3][j]);
        float4 v1 = make_float4(acc[4][j], acc[5][j], acc[6][j], acc[7][j]);
        *(float4*)&out[base]     = v0;
        *(float4*)&out[base + 4] = v1;
    }
}

// ---------------------------------------------------------------------------
// Kernel 2: 7x7 windowed similarity + positional bias.
// Block: one 8x8 pixel tile of one batch. 256 threads = 64 pixels x 4 channel
// chunks (32 channels each). Each thread keeps 49 accumulators in registers.
// smem: k halo (14x14 px x 128 ch, channel-major), q tile (channel-major),
// reduction buffers, rel tables.
// ---------------------------------------------------------------------------
#define TP    8
#define HALO  14                 // TP + 6
#define NHALO (HALO * HALO)      // 196
#define KSTR  200                // padded pixel stride in ks
#define QSTR  68                 // padded pixel stride in qs
#define RSTR  50

// float offsets within dynamic smem
#define OFF_KS   0
#define OFF_QS   (OFF_KS + 128 * KSTR)        // 25600
#define OFF_RED  (OFF_QS + 128 * QSTR)        // +8704
#define OFF_BH   (OFF_RED + 64 * RSTR)        // +3200
#define OFF_BW   (OFF_BH + 64 * 8)            // +512
#define OFF_RH   (OFF_BW + 64 * 8)            // +512
#define OFF_RW   (OFF_RH + 64 * 7)            // +448
#define SMEM_FLOATS (OFF_RW + 64 * 7)         // total 39424 floats
#define SMEM_BYTES  (SMEM_FLOATS * 4)         // 157696 B

__global__ __launch_bounds__(256) void sim_kernel(
    const float* __restrict__ rel_h,
    const float* __restrict__ rel_w,
    float* __restrict__ out)
{
    extern __shared__ float sm[];
    float* ks  = sm + OFF_KS;
    float* qs  = sm + OFF_QS;
    float* red = sm + OFF_RED;
    float* bhs = sm + OFF_BH;
    float* bws = sm + OFF_BW;
    float* rh  = sm + OFF_RH;
    float* rw  = sm + OFF_RW;

    const int tid = threadIdx.x;
    const int bb  = blockIdx.z;
    const int th0 = blockIdx.y * TP;
    const int tw0 = blockIdx.x * TP;

    // rel tables (64*7 each)
    for (int i = tid; i < 64 * 7; i += 256) {
        rh[i] = rel_h[i];
        rw[i] = rel_w[i];
    }

    // q tile: 64 px x 128 ch -> qs[c][px]   (2048 float4 loads)
    for (int i = tid; i < 64 * 32; i += 256) {
        int px = i >> 5;
        int c4 = (i & 31) * 4;
        int py = px >> 3, pxx = px & 7;
        size_t gp = (size_t)(bb * HWSZ + (th0 + py) * WWID + (tw0 + pxx));
        float4 v = *(const float4*)&g_q[gp * ACH + c4];
        qs[(c4 + 0) * QSTR + px] = v.x;
        qs[(c4 + 1) * QSTR + px] = v.y;
        qs[(c4 + 2) * QSTR + px] = v.z;
        qs[(c4 + 3) * QSTR + px] = v.w;
    }

    // k halo: 196 px x 128 ch -> ks[c][halo_px]   (6272 float4 loads)
    for (int i = tid; i < NHALO * 32; i += 256) {
        int hp = i >> 5;
        int c4 = (i & 31) * 4;
        int hy = hp / HALO, hx = hp - hy * HALO;
        int gh = th0 + hy - 3;
        int gw = tw0 + hx - 3;
        float4 v = make_float4(0.f, 0.f, 0.f, 0.f);
        if ((unsigned)gh < HH && (unsigned)gw < WWID) {
            size_t gp = (size_t)(bb * HWSZ + gh * WWID + gw);
            v = *(const float4*)&g_k[gp * ACH + c4];
        }
        ks[(c4 + 0) * KSTR + hp] = v.x;
        ks[(c4 + 1) * KSTR + hp] = v.y;
        ks[(c4 + 2) * KSTR + hp] = v.z;
        ks[(c4 + 3) * KSTR + hp] = v.w;
    }
    __syncthreads();

    // main accumulation
    const int px    = tid & 63;
    const int chunk = tid >> 6;      // 0..3 -> channels chunk*32 .. +31
    const int py = px >> 3, pxx = px & 7;
    const int c0 = chunk * 32;

    float acc[NOFF];
#pragma unroll
    for (int o = 0; o < NOFF; o++) acc[o] = 0.0f;
    float bias[KWIN];
#pragma unroll
    for (int kk = 0; kk < KWIN; kk++) bias[kk] = 0.0f;

    const float* relp   = (chunk < 2) ? rh : rw;
    const int    relofs = (chunk < 2) ? 0 : 64;
    const float* ksbase = ks + py * HALO + pxx;

    for (int c = c0; c < c0 + 32; c++) {
        float qv = qs[c * QSTR + px];
        const float* kp = ksbase + c * KSTR;
#pragma unroll
        for (int oy = 0; oy < KWIN; oy++)
#pragma unroll
            for (int ox = 0; ox < KWIN; ox++)
                acc[oy * KWIN + ox] = fmaf(kp[oy * HALO + ox], qv, acc[oy * KWIN + ox]);
        const float* rp = relp + (c - relofs) * KWIN;
#pragma unroll
        for (int kk = 0; kk < KWIN; kk++)
            bias[kk] = fmaf(rp[kk], qv, bias[kk]);
    }

    // staged reduction across the 4 channel chunks
    if (chunk == 0) {
#pragma unroll
        for (int o = 0; o < NOFF; o++) red[px * RSTR + o] = acc[o];
#pragma unroll
        for (int kk = 0; kk < KWIN; kk++) bhs[px * 8 + kk] = bias[kk];
    }
    __syncthreads();
    if (chunk == 1) {
#pragma unroll
        for (int o = 0; o < NOFF; o++) red[px * RSTR + o] += acc[o];
#pragma unroll
        for (int kk = 0; kk < KWIN; kk++) bhs[px * 8 + kk] += bias[kk];
    }
    __syncthreads();
    if (chunk == 2) {
#pragma unroll
        for (int o = 0; o < NOFF; o++) red[px * RSTR + o] += acc[o];
#pragma unroll
        for (int kk = 0; kk < KWIN; kk++) bws[px * 8 + kk] = bias[kk];
    }
    __syncthreads();
    if (chunk == 3) {
#pragma unroll
        for (int o = 0; o < NOFF; o++) red[px * RSTR + o] += acc[o];
#pragma unroll
        for (int kk = 0; kk < KWIN; kk++) bws[px * 8 + kk] += bias[kk];
    }
    __syncthreads();

    // write out: [B][H][W][7][7]
    for (int i = tid; i < 64 * NOFF; i += 256) {
        int p = i / NOFF;
        int o = i - p * NOFF;
        int oy = o / KWIN, ox = o - oy * KWIN;
        int ppy = p >> 3, ppx = p & 7;
        float v = red[p * RSTR + o] + bhs[p * 8 + oy] + bws[p * 8 + ox];
        size_t gp = (size_t)(bb * HWSZ + (th0 + ppy) * WWID + (tw0 + ppx));
        out[gp * NOFF + o] = v;
    }
}

// ---------------------------------------------------------------------------
extern "C" void kernel_launch(void* const* d_in, const int* in_sizes, int n_in,
                              void* d_out, int out_size)
{
    const float* x     = (const float*)d_in[0];   // [8,256,96,96]
    const float* w_q   = (const float*)d_in[1];   // [128,256]
    const float* w_k   = (const float*)d_in[2];   // [128,256]
    const float* rel_h = (const float*)d_in[3];   // [64,7]
    const float* rel_w = (const float*)d_in[4];   // [64,7]
    float* out = (float*)d_out;                   // [8,96,96,7,7]

    cudaFuncSetAttribute(sim_kernel, cudaFuncAttributeMaxDynamicSharedMemorySize,
                         SMEM_BYTES);

    dim3 g1(NPIX / BN, 2);
    qk_gemm_kernel<<<g1, 256>>>(x, w_q, w_k);

    dim3 g2(WWID / TP, HH / TP, BATCH);
    sim_kernel<<<g2, 256, SMEM_BYTES>>>(rel_h, rel_w, out);
}

// round 3
// speedup vs baseline: 2.2380x; 2.2380x over previous
#include <cuda_runtime.h>
#include <cuda_bf16.h>
#include <cstdint>

// ---------------- problem constants ----------------
#define HH    96
#define WWID  96
#define HWSZ  (HH * WWID)      // 9216
#define BATCH 8
#define CIN   256
#define ACH   128
#define KWIN  7
#define NOFF  (KWIN * KWIN)    // 49
#define NPIX  (BATCH * HWSZ)   // 73728

// q/k scratch, pixel-major [pixel][128ch]
__device__ float g_q[(size_t)NPIX * ACH];
__device__ float g_k[(size_t)NPIX * ACH];

// W split into bf16 hi/lo, rows 0-127 = w_q, rows 128-255 = w_k
__device__ __nv_bfloat16 g_wh[256][256];
__device__ __nv_bfloat16 g_wl[256][256];

// ---------------- helpers ----------------
__device__ __forceinline__ uint32_t smem_u32(const void* p) {
    uint32_t a;
    asm("{ .reg .u64 t; cvta.to.shared.u64 t, %1; cvt.u32.u64 %0, t; }"
        : "=r"(a) : "l"(p));
    return a;
}

__device__ __forceinline__ void split4(float4 v, uint2& hi, uint2& lo) {
    __nv_bfloat16 h0 = __float2bfloat16(v.x), h1 = __float2bfloat16(v.y);
    __nv_bfloat16 h2 = __float2bfloat16(v.z), h3 = __float2bfloat16(v.w);
    __nv_bfloat16 l0 = __float2bfloat16(v.x - __bfloat162float(h0));
    __nv_bfloat16 l1 = __float2bfloat16(v.y - __bfloat162float(h1));
    __nv_bfloat16 l2 = __float2bfloat16(v.z - __bfloat162float(h2));
    __nv_bfloat16 l3 = __float2bfloat16(v.w - __bfloat162float(h3));
    hi = make_uint2((uint32_t)__bfloat16_as_ushort(h0) | ((uint32_t)__bfloat16_as_ushort(h1) << 16),
                    (uint32_t)__bfloat16_as_ushort(h2) | ((uint32_t)__bfloat16_as_ushort(h3) << 16));
    lo = make_uint2((uint32_t)__bfloat16_as_ushort(l0) | ((uint32_t)__bfloat16_as_ushort(l1) << 16),
                    (uint32_t)__bfloat16_as_ushort(l2) | ((uint32_t)__bfloat16_as_ushort(l3) << 16));
}

__device__ __forceinline__ void ldsm_x4(uint32_t* r, uint32_t addr) {
    asm volatile("ldmatrix.sync.aligned.m8n8.x4.shared.b16 {%0,%1,%2,%3}, [%4];"
                 : "=r"(r[0]), "=r"(r[1]), "=r"(r[2]), "=r"(r[3]) : "r"(addr));
}
__device__ __forceinline__ void ldsm_x2t(uint32_t* r, uint32_t addr) {
    asm volatile("ldmatrix.sync.aligned.m8n8.x2.trans.shared.b16 {%0,%1}, [%2];"
                 : "=r"(r[0]), "=r"(r[1]) : "r"(addr));
}
__device__ __forceinline__ void mma16816(float* d, const uint32_t* a, const uint32_t* b) {
    asm volatile(
        "mma.sync.aligned.m16n8k16.row.col.f32.bf16.bf16.f32 "
        "{%0,%1,%2,%3}, {%4,%5,%6,%7}, {%8,%9}, {%0,%1,%2,%3};"
        : "+f"(d[0]), "+f"(d[1]), "+f"(d[2]), "+f"(d[3])
        : "r"(a[0]), "r"(a[1]), "r"(a[2]), "r"(a[3]), "r"(b[0]), "r"(b[1]));
}

// ---------------------------------------------------------------------------
// Pre-kernel: split W (q rows 0-127, k rows 128-255) into bf16 hi/lo.
// ---------------------------------------------------------------------------
__global__ void wsplit_kernel(const float* __restrict__ w_q,
                              const float* __restrict__ w_k)
{
    int idx = blockIdx.x * 256 + threadIdx.x;   // 16384 float4s
    int row = idx >> 6;
    int c4  = (idx & 63) * 4;
    const float* src = (row < 128) ? &w_q[row * 256 + c4]
                                   : &w_k[(row - 128) * 256 + c4];
    float4 v = *(const float4*)src;
    uint2 h, l; split4(v, h, l);
    *(uint2*)&g_wh[row][c4] = h;
    *(uint2*)&g_wl[row][c4] = l;
}

// ---------------------------------------------------------------------------
// GEMM: D[256 m][128 px] = W_split[256][256] * X[256][128px] via bf16 HMMA.
// 512 threads, 16 warps (4m x 4n). Warp tile 64x32. 3 split terms hh+lh+hl.
// smem: Ah/Al [256 rows][72 bf16] (pad), Bh/Bl [64 k][136 bf16] (pad).
// ---------------------------------------------------------------------------
#define ASTR_B  144                       // bytes per A row (64 bf16 + 8 pad)
#define BSTR_B  272                       // bytes per B row (128 bf16 + 8 pad)
#define A_BYTES (256 * ASTR_B)            // 36864
#define B_BYTES (64 * BSTR_B)             // 17408
#define AH_OFF  0
#define AL_OFF  A_BYTES
#define BH_OFF  (2 * A_BYTES)             // 73728
#define BL_OFF  (2 * A_BYTES + B_BYTES)   // 91136
#define G_SMEM  (2 * A_BYTES + 2 * B_BYTES) // 108544
#define EPSTR   136                       // floats per channel row in epilogue

__global__ __launch_bounds__(512, 1) void qk_gemm_mma(const float* __restrict__ x)
{
    extern __shared__ char gsm[];
    const uint32_t sb = smem_u32(gsm);
    const int tid = threadIdx.x;
    const int wid = tid >> 5;
    const int lid = tid & 31;
    const int mw  = wid & 3;      // m block of 64 (0-1 = q, 2-3 = k)
    const int nw  = wid >> 2;     // px block of 32

    const int n0  = blockIdx.x * 128;
    const int b   = n0 / HWSZ;
    const int hw0 = n0 % HWSZ;
    const float* __restrict__ xb = x + (size_t)b * CIN * HWSZ + hw0;

    float acc[4][4][4];
#pragma unroll
    for (int mi = 0; mi < 4; mi++)
#pragma unroll
        for (int ni = 0; ni < 4; ni++)
#pragma unroll
            for (int c = 0; c < 4; c++) acc[mi][ni][c] = 0.0f;

    for (int chunk = 0; chunk < 4; chunk++) {
        const int c0 = chunk * 64;

        // W tiles: 4096 16-byte pieces (2 splits x 256 rows x 8)
#pragma unroll
        for (int j = 0; j < 8; j++) {
            int pc  = tid + j * 512;
            int sp  = pc >> 11;
            int rem = pc & 2047;
            int row = rem >> 3;
            int kp  = rem & 7;
            const __nv_bfloat16* wsrc = sp ? &g_wl[row][c0 + kp * 8]
                                           : &g_wh[row][c0 + kp * 8];
            uint4 v = *(const uint4*)wsrc;
            *(uint4*)(gsm + (sp ? AL_OFF : AH_OFF) + row * ASTR_B + kp * 16) = v;
        }
        // X tile: 64 ch x 128 px, convert+split on the fly
#pragma unroll
        for (int j = 0; j < 4; j++) {
            int idx = tid + j * 512;
            int ch  = idx >> 5;
            int p4  = (idx & 31) * 4;
            float4 v = *(const float4*)&xb[(size_t)(c0 + ch) * HWSZ + p4];
            uint2 hv, lv; split4(v, hv, lv);
            int off = ch * BSTR_B + p4 * 2;
            *(uint2*)(gsm + BH_OFF + off) = hv;
            *(uint2*)(gsm + BL_OFF + off) = lv;
        }
        __syncthreads();

        // compute
        const int arow = (lid & 15);
        const int acol = (lid >> 4) * 16;
#pragma unroll
        for (int ks = 0; ks < 4; ks++) {
            uint32_t ah[4][4], al[4][4];
#pragma unroll
            for (int mi = 0; mi < 4; mi++) {
                uint32_t off = (uint32_t)((mw * 64 + mi * 16 + arow) * ASTR_B + ks * 32 + acol);
                ldsm_x4(ah[mi], sb + AH_OFF + off);
                ldsm_x4(al[mi], sb + AL_OFF + off);
            }
#pragma unroll
            for (int ni = 0; ni < 4; ni++) {
                uint32_t boff = (uint32_t)((ks * 16 + (lid & 15)) * BSTR_B +
                                           (nw * 32 + ni * 8) * 2);
                uint32_t bh[2], bl[2];
                ldsm_x2t(bh, sb + BH_OFF + boff);
                ldsm_x2t(bl, sb + BL_OFF + boff);
#pragma unroll
                for (int mi = 0; mi < 4; mi++) {
                    mma16816(acc[mi][ni], ah[mi], bh);   // hh
                    mma16816(acc[mi][ni], al[mi], bh);   // lh
                    mma16816(acc[mi][ni], ah[mi], bl);   // hl
                }
            }
        }
        __syncthreads();
    }

    // ---- epilogue: transpose through smem, coalesced stores ----
    float* ep = (float*)gsm;
#pragma unroll
    for (int phase = 0; phase < 2; phase++) {   // 0 = q (mw 0-1), 1 = k (mw 2-3)
        if ((mw >> 1) == phase) {
            int chb = (mw & 1) * 64 + (lid >> 2);
            int pxb = nw * 32 + (lid & 3) * 2;
#pragma unroll
            for (int mi = 0; mi < 4; mi++)
#pragma unroll
                for (int ni = 0; ni < 4; ni++) {
                    int ch = chb + mi * 16;
                    int px = pxb + ni * 8;
                    *(float2*)&ep[ch * EPSTR + px]       = make_float2(acc[mi][ni][0], acc[mi][ni][1]);
                    *(float2*)&ep[(ch + 8) * EPSTR + px] = make_float2(acc[mi][ni][2], acc[mi][ni][3]);
                }
        }
        __syncthreads();
        float* __restrict__ outp = phase ? g_k : g_q;
#pragma unroll
        for (int j = 0; j < 4; j++) {
            int i  = tid + j * 512;
            int px = i & 127;
            int c8 = (i >> 7) * 8;
            float4 v0 = make_float4(ep[(c8 + 0) * EPSTR + px], ep[(c8 + 1) * EPSTR + px],
                                    ep[(c8 + 2) * EPSTR + px], ep[(c8 + 3) * EPSTR + px]);
            float4 v1 = make_float4(ep[(c8 + 4) * EPSTR + px], ep[(c8 + 5) * EPSTR + px],
                                    ep[(c8 + 6) * EPSTR + px], ep[(c8 + 7) * EPSTR + px]);
            size_t base = (size_t)(n0 + px) * ACH + c8;
            *(float4*)&outp[base]     = v0;
            *(float4*)&outp[base + 4] = v1;
        }
        __syncthreads();
    }
}

// ---------------------------------------------------------------------------
// Kernel 2: 7x7 windowed similarity + bias. Pixel-major smem, float4 dots.
// ---------------------------------------------------------------------------
#define TP      8
#define HALO    14
#define NHALO   (HALO * HALO)        // 196
#define KSTRIDE 132
#define QSTRIDE 132
#define RSTR    50

#define OFF_KS   0
#define OFF_QS   (OFF_KS + NHALO * KSTRIDE)
#define OFF_RED  (OFF_QS + 64 * QSTRIDE)
#define OFF_BH   (OFF_RED + 64 * RSTR)
#define OFF_BW   (OFF_BH + 64 * 8)
#define OFF_RH   (OFF_BW + 64 * 8)
#define OFF_RW   (OFF_RH + 7 * 64)
#define SIM_FLOATS (OFF_RW + 7 * 64)
#define SIM_BYTES  (SIM_FLOATS * 4)

__global__ __launch_bounds__(256) void sim_kernel(
    const float* __restrict__ rel_h,
    const float* __restrict__ rel_w,
    float* __restrict__ out)
{
    extern __shared__ float sm[];
    float* ks  = sm + OFF_KS;
    float* qs  = sm + OFF_QS;
    float* red = sm + OFF_RED;
    float* bhs = sm + OFF_BH;
    float* bws = sm + OFF_BW;
    float* rht = sm + OFF_RH;
    float* rwt = sm + OFF_RW;

    const int tid = threadIdx.x;
    const int bb  = blockIdx.z;
    const int th0 = blockIdx.y * TP;
    const int tw0 = blockIdx.x * TP;

    for (int i = tid; i < 64 * 7; i += 256) {
        int c = i / 7, k = i - c * 7;
        rht[k * 64 + c] = rel_h[i];
        rwt[k * 64 + c] = rel_w[i];
    }

    for (int i = tid; i < 64 * 32; i += 256) {
        int px = i >> 5;
        int c4 = (i & 31) * 4;
        int py = px >> 3, pxx = px & 7;
        size_t gp = (size_t)(bb * HWSZ + (th0 + py) * WWID + (tw0 + pxx));
        *(float4*)&qs[px * QSTRIDE + c4] = *(const float4*)&g_q[gp * ACH + c4];
    }

    for (int i = tid; i < NHALO * 32; i += 256) {
        int hp = i >> 5;
        int c4 = (i & 31) * 4;
        int hy = hp / HALO, hx = hp - hy * HALO;
        int gh = th0 + hy - 3;
        int gw = tw0 + hx - 3;
        float4 v = make_float4(0.f, 0.f, 0.f, 0.f);
        if ((unsigned)gh < HH && (unsigned)gw < WWID) {
            size_t gp = (size_t)(bb * HWSZ + gh * WWID + gw);
            v = *(const float4*)&g_k[gp * ACH + c4];
        }
        *(float4*)&ks[hp * KSTRIDE + c4] = v;
    }
    __syncthreads();

    const int px    = tid & 63;
    const int chunk = tid >> 6;
    const int py = px >> 3, pxx = px & 7;
    const int c0  = chunk * 32;
    const int hp0 = py * HALO + pxx;

    float acc[NOFF];
#pragma unroll
    for (int o = 0; o < NOFF; o++) acc[o] = 0.0f;
    float bias[KWIN];
#pragma unroll
    for (int kk = 0; kk < KWIN; kk++) bias[kk] = 0.0f;

    const float* rt  = (chunk < 2) ? rht : rwt;
    const int    rc0 = (chunk < 2) ? c0 : c0 - 64;

    for (int ci = 0; ci < 32; ci += 4) {
        const int c = c0 + ci;
        float4 q4 = *(const float4*)&qs[px * QSTRIDE + c];
#pragma unroll
        for (int kk = 0; kk < KWIN; kk++) {
            float4 r4 = *(const float4*)&rt[kk * 64 + rc0 + ci];
            bias[kk] = fmaf(q4.x, r4.x, fmaf(q4.y, r4.y,
                       fmaf(q4.z, r4.z, fmaf(q4.w, r4.w, bias[kk]))));
        }
#pragma unroll
        for (int oy = 0; oy < KWIN; oy++)
#pragma unroll
            for (int ox = 0; ox < KWIN; ox++) {
                float4 k4 = *(const float4*)&ks[(hp0 + oy * HALO + ox) * KSTRIDE + c];
                int o = oy * KWIN + ox;
                acc[o] = fmaf(q4.x, k4.x, fmaf(q4.y, k4.y,
                         fmaf(q4.z, k4.z, fmaf(q4.w, k4.w, acc[o]))));
            }
    }

    if (chunk == 0) {
#pragma unroll
        for (int o = 0; o < NOFF; o++) red[px * RSTR + o] = acc[o];
#pragma unroll
        for (int kk = 0; kk < KWIN; kk++) bhs[px * 8 + kk] = bias[kk];
    }
    __syncthreads();
    if (chunk == 1) {
#pragma unroll
        for (int o = 0; o < NOFF; o++) red[px * RSTR + o] += acc[o];
#pragma unroll
        for (int kk = 0; kk < KWIN; kk++) bhs[px * 8 + kk] += bias[kk];
    }
    __syncthreads();
    if (chunk == 2) {
#pragma unroll
        for (int o = 0; o < NOFF; o++) red[px * RSTR + o] += acc[o];
#pragma unroll
        for (int kk = 0; kk < KWIN; kk++) bws[px * 8 + kk] = bias[kk];
    }
    __syncthreads();
    if (chunk == 3) {
#pragma unroll
        for (int o = 0; o < NOFF; o++) red[px * RSTR + o] += acc[o];
#pragma unroll
        for (int kk = 0; kk < KWIN; kk++) bws[px * 8 + kk] += bias[kk];
    }
    __syncthreads();

    for (int i = tid; i < 64 * NOFF; i += 256) {
        int p = i / NOFF;
        int o = i - p * NOFF;
        int oy = o / KWIN, ox = o - oy * KWIN;
        int ppy = p >> 3, ppx = p & 7;
        float v = red[p * RSTR + o] + bhs[p * 8 + oy] + bws[p * 8 + ox];
        size_t gp = (size_t)(bb * HWSZ + (th0 + ppy) * WWID + (tw0 + ppx));
        out[gp * NOFF + o] = v;
    }
}

// ---------------------------------------------------------------------------
extern "C" void kernel_launch(void* const* d_in, const int* in_sizes, int n_in,
                              void* d_out, int out_size)
{
    const float* x     = (const float*)d_in[0];
    const float* w_q   = (const float*)d_in[1];
    const float* w_k   = (const float*)d_in[2];
    const float* rel_h = (const float*)d_in[3];
    const float* rel_w = (const float*)d_in[4];
    float* out = (float*)d_out;

    cudaFuncSetAttribute(qk_gemm_mma, cudaFuncAttributeMaxDynamicSharedMemorySize, G_SMEM);
    cudaFuncSetAttribute(sim_kernel,  cudaFuncAttributeMaxDynamicSharedMemorySize, SIM_BYTES);

    wsplit_kernel<<<64, 256>>>(w_q, w_k);
    qk_gemm_mma<<<NPIX / 128, 512, G_SMEM>>>(x);

    dim3 g2(WWID / TP, HH / TP, BATCH);
    sim_kernel<<<g2, 256, SIM_BYTES>>>(rel_h, rel_w, out);
}

// round 4
// speedup vs baseline: 2.3934x; 1.0695x over previous
#include <cuda_runtime.h>
#include <cuda_bf16.h>
#include <cstdint>

// ---------------- problem constants ----------------
#define HH    96
#define WWID  96
#define HWSZ  (HH * WWID)      // 9216
#define BATCH 8
#define CIN   256
#define ACH   128
#define KWIN  7
#define NOFF  (KWIN * KWIN)    // 49
#define NPIX  (BATCH * HWSZ)   // 73728

// q/k scratch as bf16 hi/lo, pixel-major [pixel][128ch]
__device__ __nv_bfloat16 g_qh[(size_t)NPIX * ACH];
__device__ __nv_bfloat16 g_ql[(size_t)NPIX * ACH];
__device__ __nv_bfloat16 g_kh[(size_t)NPIX * ACH];
__device__ __nv_bfloat16 g_kl[(size_t)NPIX * ACH];

// W split into bf16 hi/lo, rows 0-127 = w_q, rows 128-255 = w_k
__device__ __nv_bfloat16 g_wh[256][256];
__device__ __nv_bfloat16 g_wl[256][256];

// ---------------- helpers ----------------
__device__ __forceinline__ uint32_t smem_u32(const void* p) {
    uint32_t a;
    asm("{ .reg .u64 t; cvta.to.shared.u64 t, %1; cvt.u32.u64 %0, t; }"
        : "=r"(a) : "l"(p));
    return a;
}

__device__ __forceinline__ void split4(float4 v, uint2& hi, uint2& lo) {
    __nv_bfloat16 h0 = __float2bfloat16(v.x), h1 = __float2bfloat16(v.y);
    __nv_bfloat16 h2 = __float2bfloat16(v.z), h3 = __float2bfloat16(v.w);
    __nv_bfloat16 l0 = __float2bfloat16(v.x - __bfloat162float(h0));
    __nv_bfloat16 l1 = __float2bfloat16(v.y - __bfloat162float(h1));
    __nv_bfloat16 l2 = __float2bfloat16(v.z - __bfloat162float(h2));
    __nv_bfloat16 l3 = __float2bfloat16(v.w - __bfloat162float(h3));
    hi = make_uint2((uint32_t)__bfloat16_as_ushort(h0) | ((uint32_t)__bfloat16_as_ushort(h1) << 16),
                    (uint32_t)__bfloat16_as_ushort(h2) | ((uint32_t)__bfloat16_as_ushort(h3) << 16));
    lo = make_uint2((uint32_t)__bfloat16_as_ushort(l0) | ((uint32_t)__bfloat16_as_ushort(l1) << 16),
                    (uint32_t)__bfloat16_as_ushort(l2) | ((uint32_t)__bfloat16_as_ushort(l3) << 16));
}

__device__ __forceinline__ void ldsm_x4(uint32_t* r, uint32_t addr) {
    asm volatile("ldmatrix.sync.aligned.m8n8.x4.shared.b16 {%0,%1,%2,%3}, [%4];"
                 : "=r"(r[0]), "=r"(r[1]), "=r"(r[2]), "=r"(r[3]) : "r"(addr));
}
__device__ __forceinline__ void ldsm_x2t(uint32_t* r, uint32_t addr) {
    asm volatile("ldmatrix.sync.aligned.m8n8.x2.trans.shared.b16 {%0,%1}, [%2];"
                 : "=r"(r[0]), "=r"(r[1]) : "r"(addr));
}
__device__ __forceinline__ void ldsm_x2(uint32_t* r, uint32_t addr) {
    asm volatile("ldmatrix.sync.aligned.m8n8.x2.shared.b16 {%0,%1}, [%2];"
                 : "=r"(r[0]), "=r"(r[1]) : "r"(addr));
}
__device__ __forceinline__ void mma16816(float* d, const uint32_t* a, const uint32_t* b) {
    asm volatile(
        "mma.sync.aligned.m16n8k16.row.col.f32.bf16.bf16.f32 "
        "{%0,%1,%2,%3}, {%4,%5,%6,%7}, {%8,%9}, {%0,%1,%2,%3};"
        : "+f"(d[0]), "+f"(d[1]), "+f"(d[2]), "+f"(d[3])
        : "r"(a[0]), "r"(a[1]), "r"(a[2]), "r"(a[3]), "r"(b[0]), "r"(b[1]));
}
__device__ __forceinline__ void cp_async16(uint32_t smem_addr, const void* g) {
    asm volatile("cp.async.cg.shared.global [%0], [%1], 16;" :: "r"(smem_addr), "l"(g));
}
#define CP_COMMIT() asm volatile("cp.async.commit_group;")
#define CP_WAIT0()  asm volatile("cp.async.wait_group 0;" ::: "memory")

// ---------------------------------------------------------------------------
// Pre-kernel: split W (q rows 0-127, k rows 128-255) into bf16 hi/lo.
// ---------------------------------------------------------------------------
__global__ void wsplit_kernel(const float* __restrict__ w_q,
                              const float* __restrict__ w_k)
{
    int idx = blockIdx.x * 256 + threadIdx.x;
    int row = idx >> 6;
    int c4  = (idx & 63) * 4;
    const float* src = (row < 128) ? &w_q[row * 256 + c4]
                                   : &w_k[(row - 128) * 256 + c4];
    float4 v = *(const float4*)src;
    uint2 h, l; split4(v, h, l);
    *(uint2*)&g_wh[row][c4] = h;
    *(uint2*)&g_wl[row][c4] = l;
}

// ---------------------------------------------------------------------------
// GEMM: D[256 m][128 px] = W_split * X via bf16 HMMA, double-buffered.
// 512 threads, 16 warps (4m x 4n). Warp tile 64x32. 3 split terms hh+lh+hl.
// ---------------------------------------------------------------------------
#define ASTR_B  144                       // bytes per A row (64 bf16 + pad)
#define BSTR_B  272                       // bytes per B row (128 bf16 + pad)
#define A_BYTES 36864                     // 256 * 144 (one split)
#define B_BYTES 17408                     // 64 * 272 (one split)
#define ABUF    73728                     // both splits, one buffer
#define BBUF    34816
#define BBASE   147456                    // 2 * ABUF
#define G_SMEM  217088                    // 2*ABUF + 2*BBUF
#define EPSTR   136

__global__ __launch_bounds__(512, 1) void qk_gemm_mma(const float* __restrict__ x)
{
    extern __shared__ char gsm[];
    const uint32_t sb = smem_u32(gsm);
    const int tid = threadIdx.x;
    const int wid = tid >> 5;
    const int lid = tid & 31;
    const int mw  = wid & 3;      // m block of 64 (0-1 = q, 2-3 = k)
    const int nw  = wid >> 2;     // px block of 32

    const int n0  = blockIdx.x * 128;
    const int b   = n0 / HWSZ;
    const int hw0 = n0 % HWSZ;
    const float* __restrict__ xb = x + (size_t)b * CIN * HWSZ + hw0;

    float acc[4][4][4];
#pragma unroll
    for (int mi = 0; mi < 4; mi++)
#pragma unroll
        for (int ni = 0; ni < 4; ni++)
#pragma unroll
            for (int c = 0; c < 4; c++) acc[mi][ni][c] = 0.0f;

    // ---- tile loaders ----
    auto loadW = [&](int chunk, int buf) {
        int c0 = chunk * 64;
#pragma unroll
        for (int j = 0; j < 8; j++) {
            int pc  = tid + j * 512;
            int sp  = pc >> 11;
            int rem = pc & 2047;
            int row = rem >> 3;
            int kp  = rem & 7;
            const __nv_bfloat16* wsrc = sp ? &g_wl[row][c0 + kp * 8]
                                           : &g_wh[row][c0 + kp * 8];
            cp_async16(sb + buf * ABUF + sp * A_BYTES + row * ASTR_B + kp * 16, wsrc);
        }
        CP_COMMIT();
    };
    auto loadX = [&](int chunk, int buf) {
        int c0 = chunk * 64;
        char* bbase = gsm + BBASE + buf * BBUF;
#pragma unroll
        for (int j = 0; j < 4; j++) {
            int idx = tid + j * 512;
            int ch  = idx >> 5;
            int p4  = (idx & 31) * 4;
            float4 v = *(const float4*)&xb[(size_t)(c0 + ch) * HWSZ + p4];
            uint2 hv, lv; split4(v, hv, lv);
            int off = ch * BSTR_B + p4 * 2;
            *(uint2*)(bbase + off)           = hv;
            *(uint2*)(bbase + B_BYTES + off) = lv;
        }
    };

    // prologue
    loadW(0, 0);
    loadX(0, 0);
    CP_WAIT0();
    __syncthreads();

    const int arow = (lid & 15);
    const int acol = (lid >> 4) * 16;

    for (int chunk = 0; chunk < 4; chunk++) {
        const int cur = chunk & 1;
        if (chunk < 3) {
            loadW(chunk + 1, cur ^ 1);
            loadX(chunk + 1, cur ^ 1);
        }
        const uint32_t ahb = sb + cur * ABUF;
        const uint32_t alb = ahb + A_BYTES;
        const uint32_t bhb = sb + BBASE + cur * BBUF;
        const uint32_t blb = bhb + B_BYTES;
#pragma unroll
        for (int ks = 0; ks < 4; ks++) {
            uint32_t ah[4][4], al[4][4];
#pragma unroll
            for (int mi = 0; mi < 4; mi++) {
                uint32_t off = (uint32_t)((mw * 64 + mi * 16 + arow) * ASTR_B + ks * 32 + acol);
                ldsm_x4(ah[mi], ahb + off);
                ldsm_x4(al[mi], alb + off);
            }
#pragma unroll
            for (int ni = 0; ni < 4; ni++) {
                uint32_t boff = (uint32_t)((ks * 16 + (lid & 15)) * BSTR_B +
                                           (nw * 32 + ni * 8) * 2);
                uint32_t bh[2], bl[2];
                ldsm_x2t(bh, bhb + boff);
                ldsm_x2t(bl, blb + boff);
#pragma unroll
                for (int mi = 0; mi < 4; mi++) {
                    mma16816(acc[mi][ni], ah[mi], bh);   // hh
                    mma16816(acc[mi][ni], al[mi], bh);   // lh
                    mma16816(acc[mi][ni], ah[mi], bl);   // hl
                }
            }
        }
        if (chunk < 3) CP_WAIT0();
        __syncthreads();
    }

    // ---- epilogue: transpose through smem, emit bf16 hi/lo ----
    float* ep = (float*)gsm;
#pragma unroll
    for (int phase = 0; phase < 2; phase++) {   // 0 = q (mw 0-1), 1 = k (mw 2-3)
        if ((mw >> 1) == phase) {
            int chb = (mw & 1) * 64 + (lid >> 2);
            int pxb = nw * 32 + (lid & 3) * 2;
#pragma unroll
            for (int mi = 0; mi < 4; mi++)
#pragma unroll
                for (int ni = 0; ni < 4; ni++) {
                    int ch = chb + mi * 16;
                    int px = pxb + ni * 8;
                    *(float2*)&ep[ch * EPSTR + px]       = make_float2(acc[mi][ni][0], acc[mi][ni][1]);
                    *(float2*)&ep[(ch + 8) * EPSTR + px] = make_float2(acc[mi][ni][2], acc[mi][ni][3]);
                }
        }
        __syncthreads();
        __nv_bfloat16* __restrict__ oh = phase ? g_kh : g_qh;
        __nv_bfloat16* __restrict__ ol = phase ? g_kl : g_ql;
#pragma unroll
        for (int j = 0; j < 4; j++) {
            int i  = tid + j * 512;
            int px = i & 127;
            int c8 = (i >> 7) * 8;
            uint32_t hp[4], lp[4];
#pragma unroll
            for (int t = 0; t < 4; t++) {
                float f0 = ep[(c8 + 2 * t) * EPSTR + px];
                float f1 = ep[(c8 + 2 * t + 1) * EPSTR + px];
                __nv_bfloat16 h0 = __float2bfloat16(f0), h1 = __float2bfloat16(f1);
                __nv_bfloat16 l0 = __float2bfloat16(f0 - __bfloat162float(h0));
                __nv_bfloat16 l1 = __float2bfloat16(f1 - __bfloat162float(h1));
                hp[t] = (uint32_t)__bfloat16_as_ushort(h0) | ((uint32_t)__bfloat16_as_ushort(h1) << 16);
                lp[t] = (uint32_t)__bfloat16_as_ushort(l0) | ((uint32_t)__bfloat16_as_ushort(l1) << 16);
            }
            size_t base = (size_t)(n0 + px) * ACH + c8;
            *(uint4*)&oh[base] = make_uint4(hp[0], hp[1], hp[2], hp[3]);
            *(uint4*)&ol[base] = make_uint4(lp[0], lp[1], lp[2], lp[3]);
        }
        __syncthreads();
    }
}

// ---------------------------------------------------------------------------
// Kernel 2: sim via tensor cores. Per 8x8 tile:
//   S[64, 210] = Q[64,128] . K'[210,128]^T   (3-term bf16 split)
// K' rows: 0..195 = 14x14 k halo, 196..202 = rel_h cols (ch 0-63),
//          203..209 = rel_w cols (ch 64-127), 210..223 zero pad.
// Epilogue gathers 49 window cols + 2 bias cols per pixel.
// ---------------------------------------------------------------------------
#define TP     8
#define HALO   14
#define SSTRB  272                   // bytes per 128-ch bf16 row + pad
#define SQH    0
#define SQL    17408                 // 64*272
#define SKH    34816
#define SKL    95744                 // SKH + 224*272
#define SIM_SMEM 156672              // SKL + 224*272
#define SS_OFF 34816                 // S (fp32) reuses K' region
#define SSTR   228                   // S floats per row

__global__ __launch_bounds__(256, 1) void sim_mma(
    const float* __restrict__ rel_h,
    const float* __restrict__ rel_w,
    float* __restrict__ out)
{
    extern __shared__ char sm[];
    const uint32_t sb = smem_u32(sm);
    const int tid = threadIdx.x;
    const int wid = tid >> 5;
    const int lid = tid & 31;
    const int bb  = blockIdx.z;
    const int th0 = blockIdx.y * TP;
    const int tw0 = blockIdx.x * TP;

    // Q fill: 2 splits x 64 rows x 16 uint4
    for (int i = tid; i < 2048; i += 256) {
        int s = i >> 10, rem = i & 1023, r = rem >> 4, c16 = rem & 15;
        int py = r >> 3, pxx = r & 7;
        size_t gp = (size_t)bb * HWSZ + (th0 + py) * WWID + (tw0 + pxx);
        uint4 v = ((const uint4*)((s ? g_ql : g_qh) + gp * ACH))[c16];
        *(uint4*)(sm + (s ? SQL : SQH) + r * SSTRB + c16 * 16) = v;
    }
    // K halo fill rows 0..195
    for (int i = tid; i < 6272; i += 256) {
        int s = (i >= 3136) ? 1 : 0;
        int rem = i - s * 3136;
        int hp = rem >> 4, c16 = rem & 15;
        int hy = hp / HALO, hx = hp - hy * HALO;
        int gh = th0 + hy - 3, gw = tw0 + hx - 3;
        uint4 v = make_uint4(0, 0, 0, 0);
        if ((unsigned)gh < HH && (unsigned)gw < WWID) {
            size_t gp = (size_t)bb * HWSZ + gh * WWID + gw;
            v = ((const uint4*)((s ? g_kl : g_kh) + gp * ACH))[c16];
        }
        *(uint4*)(sm + (s ? SKL : SKH) + hp * SSTRB + c16 * 16) = v;
    }
    // zero pad rows 210..223 (both splits): 14*17*2 uint4
    for (int i = tid; i < 476; i += 256) {
        int s = (i >= 238) ? 1 : 0;
        int rem = i - s * 238;
        int r = 210 + rem / 17, u = rem % 17;
        *(uint4*)(sm + (s ? SKL : SKH) + r * SSTRB + u * 16) = make_uint4(0, 0, 0, 0);
    }
    // bias rows 196..209, all 128 channels, both splits
    for (int i = tid; i < 3584; i += 256) {
        int s = (i >= 1792) ? 1 : 0;
        int rem = i - s * 1792;
        int r = rem >> 7, ch = rem & 127;   // r 0..13
        float v = 0.0f;
        if (r < 7)  { if (ch < 64)  v = rel_h[ch * 7 + r]; }
        else        { if (ch >= 64) v = rel_w[(ch - 64) * 7 + (r - 7)]; }
        __nv_bfloat16 h = __float2bfloat16(v);
        __nv_bfloat16 o16 = s ? __float2bfloat16(v - __bfloat162float(h)) : h;
        *(__nv_bfloat16*)(sm + (s ? SKL : SKH) + (196 + r) * SSTRB + ch * 2) = o16;
    }
    __syncthreads();

    // ---- compute: 8 warps = 2m (32 rows) x 4n (56 cols) ----
    const int mw = wid & 1;
    const int nw = wid >> 1;
    float acc[2][7][4];
#pragma unroll
    for (int mi = 0; mi < 2; mi++)
#pragma unroll
        for (int ni = 0; ni < 7; ni++)
#pragma unroll
            for (int c = 0; c < 4; c++) acc[mi][ni][c] = 0.0f;

    const int arow = lid & 15;
    const int asel = (lid >> 4) * 16;
    const int brow = lid & 7;
    const int bsel = ((lid >> 3) & 1) * 16;

#pragma unroll
    for (int ks = 0; ks < 8; ks++) {
        uint32_t ah[2][4], al[2][4];
#pragma unroll
        for (int mi = 0; mi < 2; mi++) {
            uint32_t ao = (uint32_t)((mw * 32 + mi * 16 + arow) * SSTRB + ks * 32 + asel);
            ldsm_x4(ah[mi], sb + SQH + ao);
            ldsm_x4(al[mi], sb + SQL + ao);
        }
#pragma unroll
        for (int ni = 0; ni < 7; ni++) {
            uint32_t bo = (uint32_t)((nw * 56 + ni * 8 + brow) * SSTRB + ks * 32 + bsel);
            uint32_t bh[2], bl[2];
            ldsm_x2(bh, sb + SKH + bo);
            ldsm_x2(bl, sb + SKL + bo);
#pragma unroll
            for (int mi = 0; mi < 2; mi++) {
                mma16816(acc[mi][ni], ah[mi], bh);   // hh
                mma16816(acc[mi][ni], al[mi], bh);   // lh
                mma16816(acc[mi][ni], ah[mi], bl);   // hl
            }
        }
    }
    __syncthreads();

    // ---- S store to smem (fp32), reusing K' region ----
    float* S = (float*)(sm + SS_OFF);
#pragma unroll
    for (int mi = 0; mi < 2; mi++)
#pragma unroll
        for (int ni = 0; ni < 7; ni++) {
            int m = mw * 32 + mi * 16 + (lid >> 2);
            int n = nw * 56 + ni * 8 + (lid & 3) * 2;
            *(float2*)&S[m * SSTR + n]       = make_float2(acc[mi][ni][0], acc[mi][ni][1]);
            *(float2*)&S[(m + 8) * SSTR + n] = make_float2(acc[mi][ni][2], acc[mi][ni][3]);
        }
    __syncthreads();

    // ---- gather + write out [B][H][W][7][7] ----
    for (int i = tid; i < 64 * NOFF; i += 256) {
        int px = i / NOFF, o = i - px * NOFF;
        int oy = o / KWIN, ox = o - oy * KWIN;
        int py = px >> 3, pxx = px & 7;
        int n = (py + oy) * HALO + (pxx + ox);
        float v = S[px * SSTR + n] + S[px * SSTR + 196 + oy] + S[px * SSTR + 203 + ox];
        size_t gp = (size_t)bb * HWSZ + (th0 + py) * WWID + (tw0 + pxx);
        out[gp * NOFF + o] = v;
    }
}

// ---------------------------------------------------------------------------
extern "C" void kernel_launch(void* const* d_in, const int* in_sizes, int n_in,
                              void* d_out, int out_size)
{
    const float* x     = (const float*)d_in[0];
    const float* w_q   = (const float*)d_in[1];
    const float* w_k   = (const float*)d_in[2];
    const float* rel_h = (const float*)d_in[3];
    const float* rel_w = (const float*)d_in[4];
    float* out = (float*)d_out;

    cudaFuncSetAttribute(qk_gemm_mma, cudaFuncAttributeMaxDynamicSharedMemorySize, G_SMEM);
    cudaFuncSetAttribute(sim_mma,     cudaFuncAttributeMaxDynamicSharedMemorySize, SIM_SMEM);

    wsplit_kernel<<<64, 256>>>(w_q, w_k);
    qk_gemm_mma<<<NPIX / 128, 512, G_SMEM>>>(x);

    dim3 g2(WWID / TP, HH / TP, BATCH);
    sim_mma<<<g2, 256, SIM_SMEM>>>(rel_h, rel_w, out);
}

// round 5
// speedup vs baseline: 2.8526x; 1.1918x over previous
#include <cuda_runtime.h>
#include <cuda_bf16.h>
#include <cstdint>

// ---------------- problem constants ----------------
#define HH    96
#define WWID  96
#define HWSZ  (HH * WWID)      // 9216
#define BATCH 8
#define CIN   256
#define ACH   128
#define KWIN  7
#define NOFF  (KWIN * KWIN)    // 49
#define NPIX  (BATCH * HWSZ)   // 73728

// q/k scratch as bf16 hi/lo, pixel-major [pixel][128ch]
__device__ __nv_bfloat16 g_qh[(size_t)NPIX * ACH];
__device__ __nv_bfloat16 g_ql[(size_t)NPIX * ACH];
__device__ __nv_bfloat16 g_kh[(size_t)NPIX * ACH];
__device__ __nv_bfloat16 g_kl[(size_t)NPIX * ACH];

// W split into bf16 hi/lo, rows 0-127 = w_q, rows 128-255 = w_k
__device__ __nv_bfloat16 g_wh[256][256];
__device__ __nv_bfloat16 g_wl[256][256];

// ---------------- helpers ----------------
__device__ __forceinline__ uint32_t smem_u32(const void* p) {
    uint32_t a;
    asm("{ .reg .u64 t; cvta.to.shared.u64 t, %1; cvt.u32.u64 %0, t; }"
        : "=r"(a) : "l"(p));
    return a;
}

__device__ __forceinline__ void split4(float4 v, uint2& hi, uint2& lo) {
    __nv_bfloat16 h0 = __float2bfloat16(v.x), h1 = __float2bfloat16(v.y);
    __nv_bfloat16 h2 = __float2bfloat16(v.z), h3 = __float2bfloat16(v.w);
    __nv_bfloat16 l0 = __float2bfloat16(v.x - __bfloat162float(h0));
    __nv_bfloat16 l1 = __float2bfloat16(v.y - __bfloat162float(h1));
    __nv_bfloat16 l2 = __float2bfloat16(v.z - __bfloat162float(h2));
    __nv_bfloat16 l3 = __float2bfloat16(v.w - __bfloat162float(h3));
    hi = make_uint2((uint32_t)__bfloat16_as_ushort(h0) | ((uint32_t)__bfloat16_as_ushort(h1) << 16),
                    (uint32_t)__bfloat16_as_ushort(h2) | ((uint32_t)__bfloat16_as_ushort(h3) << 16));
    lo = make_uint2((uint32_t)__bfloat16_as_ushort(l0) | ((uint32_t)__bfloat16_as_ushort(l1) << 16),
                    (uint32_t)__bfloat16_as_ushort(l2) | ((uint32_t)__bfloat16_as_ushort(l3) << 16));
}

__device__ __forceinline__ void ldsm_x4(uint32_t* r, uint32_t addr) {
    asm volatile("ldmatrix.sync.aligned.m8n8.x4.shared.b16 {%0,%1,%2,%3}, [%4];"
                 : "=r"(r[0]), "=r"(r[1]), "=r"(r[2]), "=r"(r[3]) : "r"(addr));
}
__device__ __forceinline__ void ldsm_x2t(uint32_t* r, uint32_t addr) {
    asm volatile("ldmatrix.sync.aligned.m8n8.x2.trans.shared.b16 {%0,%1}, [%2];"
                 : "=r"(r[0]), "=r"(r[1]) : "r"(addr));
}
__device__ __forceinline__ void ldsm_x2(uint32_t* r, uint32_t addr) {
    asm volatile("ldmatrix.sync.aligned.m8n8.x2.shared.b16 {%0,%1}, [%2];"
                 : "=r"(r[0]), "=r"(r[1]) : "r"(addr));
}
__device__ __forceinline__ void mma16816(float* d, const uint32_t* a, const uint32_t* b) {
    asm volatile(
        "mma.sync.aligned.m16n8k16.row.col.f32.bf16.bf16.f32 "
        "{%0,%1,%2,%3}, {%4,%5,%6,%7}, {%8,%9}, {%0,%1,%2,%3};"
        : "+f"(d[0]), "+f"(d[1]), "+f"(d[2]), "+f"(d[3])
        : "r"(a[0]), "r"(a[1]), "r"(a[2]), "r"(a[3]), "r"(b[0]), "r"(b[1]));
}
__device__ __forceinline__ void cp_async16(uint32_t smem_addr, const void* g) {
    asm volatile("cp.async.cg.shared.global [%0], [%1], 16;" :: "r"(smem_addr), "l"(g));
}
__device__ __forceinline__ void cp_async16z(uint32_t smem_addr, const void* g, int sz) {
    asm volatile("cp.async.cg.shared.global [%0], [%1], 16, %2;"
                 :: "r"(smem_addr), "l"(g), "r"(sz));
}
#define CP_COMMIT() asm volatile("cp.async.commit_group;")
#define CP_WAIT0()  asm volatile("cp.async.wait_group 0;" ::: "memory")

// ---------------------------------------------------------------------------
// Pre-kernel: split W (q rows 0-127, k rows 128-255) into bf16 hi/lo.
// ---------------------------------------------------------------------------
__global__ void wsplit_kernel(const float* __restrict__ w_q,
                              const float* __restrict__ w_k)
{
    int idx = blockIdx.x * 256 + threadIdx.x;
    int row = idx >> 6;
    int c4  = (idx & 63) * 4;
    const float* src = (row < 128) ? &w_q[row * 256 + c4]
                                   : &w_k[(row - 128) * 256 + c4];
    float4 v = *(const float4*)src;
    uint2 h, l; split4(v, h, l);
    *(uint2*)&g_wh[row][c4] = h;
    *(uint2*)&g_wl[row][c4] = l;
}

// ---------------------------------------------------------------------------
// GEMM: D[256 m][128 px] = W_split * X via bf16 HMMA.
// Double-buffered smem; W via cp.async, X via register-prefetch pipeline.
// 512 threads, 16 warps (4m x 4n). Warp tile 64x32. 3 split terms hh+lh+hl.
// ---------------------------------------------------------------------------
#define ASTR_B  144
#define BSTR_B  272
#define A_BYTES 36864
#define B_BYTES 17408
#define ABUF    73728
#define BBUF    34816
#define BBASE   147456
#define G_SMEM  217088
#define EPSTR   136

__global__ __launch_bounds__(512, 1) void qk_gemm_mma(const float* __restrict__ x)
{
    extern __shared__ char gsm[];
    const uint32_t sb = smem_u32(gsm);
    const int tid = threadIdx.x;
    const int wid = tid >> 5;
    const int lid = tid & 31;
    const int mw  = wid & 3;
    const int nw  = wid >> 2;

    const int n0  = blockIdx.x * 128;
    const int b   = n0 / HWSZ;
    const int hw0 = n0 % HWSZ;
    const float* __restrict__ xb = x + (size_t)b * CIN * HWSZ + hw0;

    float acc[4][4][4];
#pragma unroll
    for (int mi = 0; mi < 4; mi++)
#pragma unroll
        for (int ni = 0; ni < 4; ni++)
#pragma unroll
            for (int c = 0; c < 4; c++) acc[mi][ni][c] = 0.0f;

    auto loadW = [&](int chunk, int buf) {
        int c0 = chunk * 64;
#pragma unroll
        for (int j = 0; j < 8; j++) {
            int pc  = tid + j * 512;
            int sp  = pc >> 11;
            int rem = pc & 2047;
            int row = rem >> 3;
            int kp  = rem & 7;
            const __nv_bfloat16* wsrc = sp ? &g_wl[row][c0 + kp * 8]
                                           : &g_wh[row][c0 + kp * 8];
            cp_async16(sb + buf * ABUF + sp * A_BYTES + row * ASTR_B + kp * 16, wsrc);
        }
        CP_COMMIT();
    };
    auto ldgX = [&](int chunk, float4* xr) {
        int c0 = chunk * 64;
#pragma unroll
        for (int j = 0; j < 4; j++) {
            int idx = tid + j * 512;
            int ch  = idx >> 5;
            int p4  = (idx & 31) * 4;
            xr[j] = *(const float4*)&xb[(size_t)(c0 + ch) * HWSZ + p4];
        }
    };
    auto stsX = [&](const float4* xr, int buf) {
        char* bbase = gsm + BBASE + buf * BBUF;
#pragma unroll
        for (int j = 0; j < 4; j++) {
            int idx = tid + j * 512;
            int ch  = idx >> 5;
            int p4  = (idx & 31) * 4;
            uint2 hv, lv; split4(xr[j], hv, lv);
            int off = ch * BSTR_B + p4 * 2;
            *(uint2*)(bbase + off)           = hv;
            *(uint2*)(bbase + B_BYTES + off) = lv;
        }
    };

    // prologue
    float4 xr[4];
    loadW(0, 0);
    ldgX(0, xr);
    stsX(xr, 0);
    CP_WAIT0();
    __syncthreads();

    const int arow = (lid & 15);
    const int acol = (lid >> 4) * 16;

    for (int chunk = 0; chunk < 4; chunk++) {
        const int cur = chunk & 1;
        if (chunk < 3) {
            loadW(chunk + 1, cur ^ 1);   // async into alt buffer
            ldgX(chunk + 1, xr);         // LDG issued now, consumed after compute
        }
        const uint32_t ahb = sb + cur * ABUF;
        const uint32_t alb = ahb + A_BYTES;
        const uint32_t bhb = sb + BBASE + cur * BBUF;
        const uint32_t blb = bhb + B_BYTES;
#pragma unroll
        for (int ks = 0; ks < 4; ks++) {
            uint32_t ah[4][4], al[4][4];
#pragma unroll
            for (int mi = 0; mi < 4; mi++) {
                uint32_t off = (uint32_t)((mw * 64 + mi * 16 + arow) * ASTR_B + ks * 32 + acol);
                ldsm_x4(ah[mi], ahb + off);
                ldsm_x4(al[mi], alb + off);
            }
#pragma unroll
            for (int ni = 0; ni < 4; ni++) {
                uint32_t boff = (uint32_t)((ks * 16 + (lid & 15)) * BSTR_B +
                                           (nw * 32 + ni * 8) * 2);
                uint32_t bh[2], bl[2];
                ldsm_x2t(bh, bhb + boff);
                ldsm_x2t(bl, blb + boff);
#pragma unroll
                for (int mi = 0; mi < 4; mi++) {
                    mma16816(acc[mi][ni], ah[mi], bh);   // hh
                    mma16816(acc[mi][ni], al[mi], bh);   // lh
                    mma16816(acc[mi][ni], ah[mi], bl);   // hl
                }
            }
        }
        if (chunk < 3) {
            stsX(xr, cur ^ 1);
            CP_WAIT0();
        }
        __syncthreads();
    }

    // ---- epilogue: transpose through smem, emit bf16 hi/lo ----
    float* ep = (float*)gsm;
#pragma unroll
    for (int phase = 0; phase < 2; phase++) {
        if ((mw >> 1) == phase) {
            int chb = (mw & 1) * 64 + (lid >> 2);
            int pxb = nw * 32 + (lid & 3) * 2;
#pragma unroll
            for (int mi = 0; mi < 4; mi++)
#pragma unroll
                for (int ni = 0; ni < 4; ni++) {
                    int ch = chb + mi * 16;
                    int px = pxb + ni * 8;
                    *(float2*)&ep[ch * EPSTR + px]       = make_float2(acc[mi][ni][0], acc[mi][ni][1]);
                    *(float2*)&ep[(ch + 8) * EPSTR + px] = make_float2(acc[mi][ni][2], acc[mi][ni][3]);
                }
        }
        __syncthreads();
        __nv_bfloat16* __restrict__ oh = phase ? g_kh : g_qh;
        __nv_bfloat16* __restrict__ ol = phase ? g_kl : g_ql;
#pragma unroll
        for (int j = 0; j < 4; j++) {
            int i  = tid + j * 512;
            int px = i & 127;
            int c8 = (i >> 7) * 8;
            uint32_t hp[4], lp[4];
#pragma unroll
            for (int t = 0; t < 4; t++) {
                float f0 = ep[(c8 + 2 * t) * EPSTR + px];
                float f1 = ep[(c8 + 2 * t + 1) * EPSTR + px];
                __nv_bfloat16 h0 = __float2bfloat16(f0), h1 = __float2bfloat16(f1);
                __nv_bfloat16 l0 = __float2bfloat16(f0 - __bfloat162float(h0));
                __nv_bfloat16 l1 = __float2bfloat16(f1 - __bfloat162float(h1));
                hp[t] = (uint32_t)__bfloat16_as_ushort(h0) | ((uint32_t)__bfloat16_as_ushort(h1) << 16);
                lp[t] = (uint32_t)__bfloat16_as_ushort(l0) | ((uint32_t)__bfloat16_as_ushort(l1) << 16);
            }
            size_t base = (size_t)(n0 + px) * ACH + c8;
            *(uint4*)&oh[base] = make_uint4(hp[0], hp[1], hp[2], hp[3]);
            *(uint4*)&ol[base] = make_uint4(lp[0], lp[1], lp[2], lp[3]);
        }
        __syncthreads();
    }
}

// ---------------------------------------------------------------------------
// Kernel 2: sim via tensor cores, cp.async fills.
//   S[64, 210] = Q[64,128] . K'[210,128]^T   (3-term bf16 split)
// K' rows: 0..195 = 14x14 k halo, 196..202 = rel_h cols (ch 0-63),
//          203..209 = rel_w cols (ch 64-127), 210..223 zero pad.
// ---------------------------------------------------------------------------
#define TP     8
#define HALO   14
#define SSTRB  272
#define SQH    0
#define SQL    17408
#define SKH    34816
#define SKL    95744
#define SIM_SMEM 156672
#define SS_OFF 34816
#define SSTR   228

__global__ __launch_bounds__(256, 1) void sim_mma(
    const float* __restrict__ rel_h,
    const float* __restrict__ rel_w,
    float* __restrict__ out)
{
    extern __shared__ char sm[];
    const uint32_t sb = smem_u32(sm);
    const int tid = threadIdx.x;
    const int wid = tid >> 5;
    const int lid = tid & 31;
    const int bb  = blockIdx.z;
    const int th0 = blockIdx.y * TP;
    const int tw0 = blockIdx.x * TP;

    // Q fill via cp.async: 2 splits x 64 rows x 16 uint4
    for (int i = tid; i < 2048; i += 256) {
        int s = i >> 10, rem = i & 1023, r = rem >> 4, c16 = rem & 15;
        int py = r >> 3, pxx = r & 7;
        size_t gp = (size_t)bb * HWSZ + (th0 + py) * WWID + (tw0 + pxx);
        const __nv_bfloat16* src = (s ? g_ql : g_qh) + gp * ACH + c16 * 8;
        cp_async16(sb + (s ? SQL : SQH) + r * SSTRB + c16 * 16, src);
    }
    // K halo fill via cp.async (zero-fill OOB): rows 0..195
    for (int i = tid; i < 6272; i += 256) {
        int s = (i >= 3136) ? 1 : 0;
        int rem = i - s * 3136;
        int hp = rem >> 4, c16 = rem & 15;
        int hy = hp / HALO, hx = hp - hy * HALO;
        int gh = th0 + hy - 3, gw = tw0 + hx - 3;
        bool ok = ((unsigned)gh < HH) && ((unsigned)gw < WWID);
        size_t gp = ok ? ((size_t)bb * HWSZ + gh * WWID + gw) : 0;
        const __nv_bfloat16* src = (s ? g_kl : g_kh) + gp * ACH + c16 * 8;
        cp_async16z(sb + (s ? SKL : SKH) + hp * SSTRB + c16 * 16, src, ok ? 16 : 0);
    }
    CP_COMMIT();

    // zero pad rows 210..223 (both splits)
    for (int i = tid; i < 476; i += 256) {
        int s = (i >= 238) ? 1 : 0;
        int rem = i - s * 238;
        int r = 210 + rem / 17, u = rem % 17;
        *(uint4*)(sm + (s ? SKL : SKH) + r * SSTRB + u * 16) = make_uint4(0, 0, 0, 0);
    }
    // bias rows 196..209
    for (int i = tid; i < 3584; i += 256) {
        int s = (i >= 1792) ? 1 : 0;
        int rem = i - s * 1792;
        int r = rem >> 7, ch = rem & 127;
        float v = 0.0f;
        if (r < 7)  { if (ch < 64)  v = rel_h[ch * 7 + r]; }
        else        { if (ch >= 64) v = rel_w[(ch - 64) * 7 + (r - 7)]; }
        __nv_bfloat16 h = __float2bfloat16(v);
        __nv_bfloat16 o16 = s ? __float2bfloat16(v - __bfloat162float(h)) : h;
        *(__nv_bfloat16*)(sm + (s ? SKL : SKH) + (196 + r) * SSTRB + ch * 2) = o16;
    }
    CP_WAIT0();
    __syncthreads();

    // ---- compute: 8 warps = 2m (32 rows) x 4n (56 cols) ----
    const int mw = wid & 1;
    const int nw = wid >> 1;
    float acc[2][7][4];
#pragma unroll
    for (int mi = 0; mi < 2; mi++)
#pragma unroll
        for (int ni = 0; ni < 7; ni++)
#pragma unroll
            for (int c = 0; c < 4; c++) acc[mi][ni][c] = 0.0f;

    const int arow = lid & 15;
    const int asel = (lid >> 4) * 16;
    const int brow = lid & 7;
    const int bsel = ((lid >> 3) & 1) * 16;

#pragma unroll
    for (int ks = 0; ks < 8; ks++) {
        uint32_t ah[2][4], al[2][4];
#pragma unroll
        for (int mi = 0; mi < 2; mi++) {
            uint32_t ao = (uint32_t)((mw * 32 + mi * 16 + arow) * SSTRB + ks * 32 + asel);
            ldsm_x4(ah[mi], sb + SQH + ao);
            ldsm_x4(al[mi], sb + SQL + ao);
        }
#pragma unroll
        for (int ni = 0; ni < 7; ni++) {
            uint32_t bo = (uint32_t)((nw * 56 + ni * 8 + brow) * SSTRB + ks * 32 + bsel);
            uint32_t bh[2], bl[2];
            ldsm_x2(bh, sb + SKH + bo);
            ldsm_x2(bl, sb + SKL + bo);
#pragma unroll
            for (int mi = 0; mi < 2; mi++) {
                mma16816(acc[mi][ni], ah[mi], bh);   // hh
                mma16816(acc[mi][ni], al[mi], bh);   // lh
                mma16816(acc[mi][ni], ah[mi], bl);   // hl
            }
        }
    }
    __syncthreads();

    // ---- S store to smem (fp32), reusing K' region ----
    float* S = (float*)(sm + SS_OFF);
#pragma unroll
    for (int mi = 0; mi < 2; mi++)
#pragma unroll
        for (int ni = 0; ni < 7; ni++) {
            int m = mw * 32 + mi * 16 + (lid >> 2);
            int n = nw * 56 + ni * 8 + (lid & 3) * 2;
            *(float2*)&S[m * SSTR + n]       = make_float2(acc[mi][ni][0], acc[mi][ni][1]);
            *(float2*)&S[(m + 8) * SSTR + n] = make_float2(acc[mi][ni][2], acc[mi][ni][3]);
        }
    __syncthreads();

    // ---- gather + write out [B][H][W][7][7] ----
    for (int i = tid; i < 64 * NOFF; i += 256) {
        int px = i / NOFF, o = i - px * NOFF;
        int oy = o / KWIN, ox = o - oy * KWIN;
        int py = px >> 3, pxx = px & 7;
        int n = (py + oy) * HALO + (pxx + ox);
        float v = S[px * SSTR + n] + S[px * SSTR + 196 + oy] + S[px * SSTR + 203 + ox];
        size_t gp = (size_t)bb * HWSZ + (th0 + py) * WWID + (tw0 + pxx);
        out[gp * NOFF + o] = v;
    }
}

// ---------------------------------------------------------------------------
extern "C" void kernel_launch(void* const* d_in, const int* in_sizes, int n_in,
                              void* d_out, int out_size)
{
    const float* x     = (const float*)d_in[0];
    const float* w_q   = (const float*)d_in[1];
    const float* w_k   = (const float*)d_in[2];
    const float* rel_h = (const float*)d_in[3];
    const float* rel_w = (const float*)d_in[4];
    float* out = (float*)d_out;

    cudaFuncSetAttribute(qk_gemm_mma, cudaFuncAttributeMaxDynamicSharedMemorySize, G_SMEM);
    cudaFuncSetAttribute(sim_mma,     cudaFuncAttributeMaxDynamicSharedMemorySize, SIM_SMEM);

    wsplit_kernel<<<64, 256>>>(w_q, w_k);
    qk_gemm_mma<<<NPIX / 128, 512, G_SMEM>>>(x);

    dim3 g2(WWID / TP, HH / TP, BATCH);
    sim_mma<<<g2, 256, SIM_SMEM>>>(rel_h, rel_w, out);
}

// round 6
// speedup vs baseline: 3.0160x; 1.0573x over previous
#include <cuda_runtime.h>
#include <cuda_bf16.h>
#include <cstdint>

// ---------------- problem constants ----------------
#define HH    96
#define WWID  96
#define HWSZ  (HH * WWID)      // 9216
#define BATCH 8
#define CIN   256
#define ACH   128
#define KWIN  7
#define NOFF  (KWIN * KWIN)    // 49
#define NPIX  (BATCH * HWSZ)   // 73728

// q/k scratch as bf16 hi/lo, pixel-major [pixel][128ch]
__device__ __nv_bfloat16 g_qh[(size_t)NPIX * ACH];
__device__ __nv_bfloat16 g_ql[(size_t)NPIX * ACH];
__device__ __nv_bfloat16 g_kh[(size_t)NPIX * ACH];
__device__ __nv_bfloat16 g_kl[(size_t)NPIX * ACH];

// W split into bf16 hi/lo, rows 0-127 = w_q, rows 128-255 = w_k
__device__ __nv_bfloat16 g_wh[256][256];
__device__ __nv_bfloat16 g_wl[256][256];

// ---------------- helpers ----------------
__device__ __forceinline__ uint32_t smem_u32(const void* p) {
    uint32_t a;
    asm("{ .reg .u64 t; cvta.to.shared.u64 t, %1; cvt.u32.u64 %0, t; }"
        : "=r"(a) : "l"(p));
    return a;
}

__device__ __forceinline__ void split4(float4 v, uint2& hi, uint2& lo) {
    __nv_bfloat16 h0 = __float2bfloat16(v.x), h1 = __float2bfloat16(v.y);
    __nv_bfloat16 h2 = __float2bfloat16(v.z), h3 = __float2bfloat16(v.w);
    __nv_bfloat16 l0 = __float2bfloat16(v.x - __bfloat162float(h0));
    __nv_bfloat16 l1 = __float2bfloat16(v.y - __bfloat162float(h1));
    __nv_bfloat16 l2 = __float2bfloat16(v.z - __bfloat162float(h2));
    __nv_bfloat16 l3 = __float2bfloat16(v.w - __bfloat162float(h3));
    hi = make_uint2((uint32_t)__bfloat16_as_ushort(h0) | ((uint32_t)__bfloat16_as_ushort(h1) << 16),
                    (uint32_t)__bfloat16_as_ushort(h2) | ((uint32_t)__bfloat16_as_ushort(h3) << 16));
    lo = make_uint2((uint32_t)__bfloat16_as_ushort(l0) | ((uint32_t)__bfloat16_as_ushort(l1) << 16),
                    (uint32_t)__bfloat16_as_ushort(l2) | ((uint32_t)__bfloat16_as_ushort(l3) << 16));
}

__device__ __forceinline__ void ldsm_x4(uint32_t* r, uint32_t addr) {
    asm volatile("ldmatrix.sync.aligned.m8n8.x4.shared.b16 {%0,%1,%2,%3}, [%4];"
                 : "=r"(r[0]), "=r"(r[1]), "=r"(r[2]), "=r"(r[3]) : "r"(addr));
}
__device__ __forceinline__ void ldsm_x2t(uint32_t* r, uint32_t addr) {
    asm volatile("ldmatrix.sync.aligned.m8n8.x2.trans.shared.b16 {%0,%1}, [%2];"
                 : "=r"(r[0]), "=r"(r[1]) : "r"(addr));
}
__device__ __forceinline__ void ldsm_x2(uint32_t* r, uint32_t addr) {
    asm volatile("ldmatrix.sync.aligned.m8n8.x2.shared.b16 {%0,%1}, [%2];"
                 : "=r"(r[0]), "=r"(r[1]) : "r"(addr));
}
__device__ __forceinline__ void mma16816(float* d, const uint32_t* a, const uint32_t* b) {
    asm volatile(
        "mma.sync.aligned.m16n8k16.row.col.f32.bf16.bf16.f32 "
        "{%0,%1,%2,%3}, {%4,%5,%6,%7}, {%8,%9}, {%0,%1,%2,%3};"
        : "+f"(d[0]), "+f"(d[1]), "+f"(d[2]), "+f"(d[3])
        : "r"(a[0]), "r"(a[1]), "r"(a[2]), "r"(a[3]), "r"(b[0]), "r"(b[1]));
}
__device__ __forceinline__ void cp_async16(uint32_t smem_addr, const void* g) {
    asm volatile("cp.async.cg.shared.global [%0], [%1], 16;" :: "r"(smem_addr), "l"(g));
}
__device__ __forceinline__ void cp_async16z(uint32_t smem_addr, const void* g, int sz) {
    asm volatile("cp.async.cg.shared.global [%0], [%1], 16, %2;"
                 :: "r"(smem_addr), "l"(g), "r"(sz));
}
#define CP_COMMIT() asm volatile("cp.async.commit_group;")
#define CP_WAIT0()  asm volatile("cp.async.wait_group 0;" ::: "memory")

// ---------------------------------------------------------------------------
// Pre-kernel: split W into bf16 hi/lo.
// ---------------------------------------------------------------------------
__global__ void wsplit_kernel(const float* __restrict__ w_q,
                              const float* __restrict__ w_k)
{
    int idx = blockIdx.x * 256 + threadIdx.x;
    int row = idx >> 6;
    int c4  = (idx & 63) * 4;
    const float* src = (row < 128) ? &w_q[row * 256 + c4]
                                   : &w_k[(row - 128) * 256 + c4];
    float4 v = *(const float4*)src;
    uint2 h, l; split4(v, h, l);
    *(uint2*)&g_wh[row][c4] = h;
    *(uint2*)&g_wl[row][c4] = l;
}

// ---------------------------------------------------------------------------
// GEMM: D[256 m][128 px] = W_split * X via bf16 HMMA.  (unchanged from R5)
// ---------------------------------------------------------------------------
#define ASTR_B  144
#define BSTR_B  272
#define A_BYTES 36864
#define B_BYTES 17408
#define ABUF    73728
#define BBUF    34816
#define BBASE   147456
#define G_SMEM  217088
#define EPSTR   136

__global__ __launch_bounds__(512, 1) void qk_gemm_mma(const float* __restrict__ x)
{
    extern __shared__ char gsm[];
    const uint32_t sb = smem_u32(gsm);
    const int tid = threadIdx.x;
    const int wid = tid >> 5;
    const int lid = tid & 31;
    const int mw  = wid & 3;
    const int nw  = wid >> 2;

    const int n0  = blockIdx.x * 128;
    const int b   = n0 / HWSZ;
    const int hw0 = n0 % HWSZ;
    const float* __restrict__ xb = x + (size_t)b * CIN * HWSZ + hw0;

    float acc[4][4][4];
#pragma unroll
    for (int mi = 0; mi < 4; mi++)
#pragma unroll
        for (int ni = 0; ni < 4; ni++)
#pragma unroll
            for (int c = 0; c < 4; c++) acc[mi][ni][c] = 0.0f;

    auto loadW = [&](int chunk, int buf) {
        int c0 = chunk * 64;
#pragma unroll
        for (int j = 0; j < 8; j++) {
            int pc  = tid + j * 512;
            int sp  = pc >> 11;
            int rem = pc & 2047;
            int row = rem >> 3;
            int kp  = rem & 7;
            const __nv_bfloat16* wsrc = sp ? &g_wl[row][c0 + kp * 8]
                                           : &g_wh[row][c0 + kp * 8];
            cp_async16(sb + buf * ABUF + sp * A_BYTES + row * ASTR_B + kp * 16, wsrc);
        }
        CP_COMMIT();
    };
    auto ldgX = [&](int chunk, float4* xr) {
        int c0 = chunk * 64;
#pragma unroll
        for (int j = 0; j < 4; j++) {
            int idx = tid + j * 512;
            int ch  = idx >> 5;
            int p4  = (idx & 31) * 4;
            xr[j] = *(const float4*)&xb[(size_t)(c0 + ch) * HWSZ + p4];
        }
    };
    auto stsX = [&](const float4* xr, int buf) {
        char* bbase = gsm + BBASE + buf * BBUF;
#pragma unroll
        for (int j = 0; j < 4; j++) {
            int idx = tid + j * 512;
            int ch  = idx >> 5;
            int p4  = (idx & 31) * 4;
            uint2 hv, lv; split4(xr[j], hv, lv);
            int off = ch * BSTR_B + p4 * 2;
            *(uint2*)(bbase + off)           = hv;
            *(uint2*)(bbase + B_BYTES + off) = lv;
        }
    };

    float4 xr[4];
    loadW(0, 0);
    ldgX(0, xr);
    stsX(xr, 0);
    CP_WAIT0();
    __syncthreads();

    const int arow = (lid & 15);
    const int acol = (lid >> 4) * 16;

    for (int chunk = 0; chunk < 4; chunk++) {
        const int cur = chunk & 1;
        if (chunk < 3) {
            loadW(chunk + 1, cur ^ 1);
            ldgX(chunk + 1, xr);
        }
        const uint32_t ahb = sb + cur * ABUF;
        const uint32_t alb = ahb + A_BYTES;
        const uint32_t bhb = sb + BBASE + cur * BBUF;
        const uint32_t blb = bhb + B_BYTES;
#pragma unroll
        for (int ks = 0; ks < 4; ks++) {
            uint32_t ah[4][4], al[4][4];
#pragma unroll
            for (int mi = 0; mi < 4; mi++) {
                uint32_t off = (uint32_t)((mw * 64 + mi * 16 + arow) * ASTR_B + ks * 32 + acol);
                ldsm_x4(ah[mi], ahb + off);
                ldsm_x4(al[mi], alb + off);
            }
#pragma unroll
            for (int ni = 0; ni < 4; ni++) {
                uint32_t boff = (uint32_t)((ks * 16 + (lid & 15)) * BSTR_B +
                                           (nw * 32 + ni * 8) * 2);
                uint32_t bh[2], bl[2];
                ldsm_x2t(bh, bhb + boff);
                ldsm_x2t(bl, blb + boff);
#pragma unroll
                for (int mi = 0; mi < 4; mi++) {
                    mma16816(acc[mi][ni], ah[mi], bh);
                    mma16816(acc[mi][ni], al[mi], bh);
                    mma16816(acc[mi][ni], ah[mi], bl);
                }
            }
        }
        if (chunk < 3) {
            stsX(xr, cur ^ 1);
            CP_WAIT0();
        }
        __syncthreads();
    }

    float* ep = (float*)gsm;
#pragma unroll
    for (int phase = 0; phase < 2; phase++) {
        if ((mw >> 1) == phase) {
            int chb = (mw & 1) * 64 + (lid >> 2);
            int pxb = nw * 32 + (lid & 3) * 2;
#pragma unroll
            for (int mi = 0; mi < 4; mi++)
#pragma unroll
                for (int ni = 0; ni < 4; ni++) {
                    int ch = chb + mi * 16;
                    int px = pxb + ni * 8;
                    *(float2*)&ep[ch * EPSTR + px]       = make_float2(acc[mi][ni][0], acc[mi][ni][1]);
                    *(float2*)&ep[(ch + 8) * EPSTR + px] = make_float2(acc[mi][ni][2], acc[mi][ni][3]);
                }
        }
        __syncthreads();
        __nv_bfloat16* __restrict__ oh = phase ? g_kh : g_qh;
        __nv_bfloat16* __restrict__ ol = phase ? g_kl : g_ql;
#pragma unroll
        for (int j = 0; j < 4; j++) {
            int i  = tid + j * 512;
            int px = i & 127;
            int c8 = (i >> 7) * 8;
            uint32_t hp[4], lp[4];
#pragma unroll
            for (int t = 0; t < 4; t++) {
                float f0 = ep[(c8 + 2 * t) * EPSTR + px];
                float f1 = ep[(c8 + 2 * t + 1) * EPSTR + px];
                __nv_bfloat16 h0 = __float2bfloat16(f0), h1 = __float2bfloat16(f1);
                __nv_bfloat16 l0 = __float2bfloat16(f0 - __bfloat162float(h0));
                __nv_bfloat16 l1 = __float2bfloat16(f1 - __bfloat162float(h1));
                hp[t] = (uint32_t)__bfloat16_as_ushort(h0) | ((uint32_t)__bfloat16_as_ushort(h1) << 16);
                lp[t] = (uint32_t)__bfloat16_as_ushort(l0) | ((uint32_t)__bfloat16_as_ushort(l1) << 16);
            }
            size_t base = (size_t)(n0 + px) * ACH + c8;
            *(uint4*)&oh[base] = make_uint4(hp[0], hp[1], hp[2], hp[3]);
            *(uint4*)&ol[base] = make_uint4(lp[0], lp[1], lp[2], lp[3]);
        }
        __syncthreads();
    }
}

// ---------------------------------------------------------------------------
// Kernel 2: sim via tensor cores, channel-split (2 x 64 ch) for 2 CTA/SM.
//   S[64, 210] = Q[64,128] . K'[210,128]^T, accumulated over 2 channel halves.
// Per half smem: Q[64][64ch] hi/lo + K'[224][64ch] hi/lo, stride 144 B.
// Bias rows 196..202 = rel_h (half 0), 203..209 = rel_w (half 1).
// ---------------------------------------------------------------------------
#define TP     8
#define HALO   14
#define CSTRB  144                       // 64 bf16 (128 B) + 16 pad
#define SQH    0
#define SQL    9216                      // 64*144
#define SKH    18432
#define SKL    50688                     // SKH + 224*144
#define SIM_SMEM 82944                   // SKL + 224*144
#define SS_OFF 18432                     // S (fp32) reuses K' region (64512 B)
#define SSTR   228

__global__ __launch_bounds__(256, 2) void sim_mma(
    const float* __restrict__ rel_h,
    const float* __restrict__ rel_w,
    float* __restrict__ out)
{
    extern __shared__ char sm[];
    const uint32_t sb = smem_u32(sm);
    const int tid = threadIdx.x;
    const int wid = tid >> 5;
    const int lid = tid & 31;
    const int bb  = blockIdx.z;
    const int th0 = blockIdx.y * TP;
    const int tw0 = blockIdx.x * TP;

    const int mw = wid & 1;
    const int nw = wid >> 1;
    float acc[2][7][4];
#pragma unroll
    for (int mi = 0; mi < 2; mi++)
#pragma unroll
        for (int ni = 0; ni < 7; ni++)
#pragma unroll
            for (int c = 0; c < 4; c++) acc[mi][ni][c] = 0.0f;

    const int arow = lid & 15;
    const int asel = (lid >> 4) * 16;
    const int brow = lid & 7;
    const int bsel = ((lid >> 3) & 1) * 16;

    bool pad_done = false;

    for (int half = 0; half < 2; half++) {
        const int ch0 = half * 64;

        // Q fill: 2 splits x 64 rows x 8 uint4
        for (int i = tid; i < 1024; i += 256) {
            int s = i >> 9, rem = i & 511, r = rem >> 3, c16 = rem & 7;
            int py = r >> 3, pxx = r & 7;
            size_t gp = (size_t)bb * HWSZ + (th0 + py) * WWID + (tw0 + pxx);
            const __nv_bfloat16* src = (s ? g_ql : g_qh) + gp * ACH + ch0 + c16 * 8;
            cp_async16(sb + (s ? SQL : SQH) + r * CSTRB + c16 * 16, src);
        }
        // K halo fill (zero-fill OOB): rows 0..195, 2 splits x 196 x 8 uint4
        for (int i = tid; i < 3136; i += 256) {
            int s = (i >= 1568) ? 1 : 0;
            int rem = i - s * 1568;
            int hp = rem >> 3, c16 = rem & 7;
            int hy = hp / HALO, hx = hp - hy * HALO;
            int gh = th0 + hy - 3, gw = tw0 + hx - 3;
            bool ok = ((unsigned)gh < HH) && ((unsigned)gw < WWID);
            size_t gp = ok ? ((size_t)bb * HWSZ + gh * WWID + gw) : 0;
            const __nv_bfloat16* src = (s ? g_kl : g_kh) + gp * ACH + ch0 + c16 * 8;
            cp_async16z(sb + (s ? SKL : SKH) + hp * CSTRB + c16 * 16, src, ok ? 16 : 0);
        }
        CP_COMMIT();

        // zero pad rows 210..223 (only needed once; S store happens after both halves)
        if (!pad_done) {
            for (int i = tid; i < 252; i += 256) {
                int s = (i >= 126) ? 1 : 0;
                int rem = i - s * 126;
                int r = 210 + rem / 9, u = rem % 9;
                *(uint4*)(sm + (s ? SKL : SKH) + r * CSTRB + u * 16) = make_uint4(0, 0, 0, 0);
            }
            pad_done = true;
        }
        // bias rows 196..209 per half: half0 -> rows 196..202 = rel_h, rest 0
        //                              half1 -> rows 203..209 = rel_w, rest 0
        for (int i = tid; i < 1792; i += 256) {
            int s = (i >= 896) ? 1 : 0;
            int rem = i - s * 896;
            int r = rem >> 6, ch = rem & 63;   // r 0..13, local channel
            float v = 0.0f;
            if (half == 0) { if (r < 7)  v = rel_h[ch * 7 + r]; }
            else           { if (r >= 7) v = rel_w[ch * 7 + (r - 7)]; }
            __nv_bfloat16 h = __float2bfloat16(v);
            __nv_bfloat16 o16 = s ? __float2bfloat16(v - __bfloat162float(h)) : h;
            *(__nv_bfloat16*)(sm + (s ? SKL : SKH) + (196 + r) * CSTRB + ch * 2) = o16;
        }
        CP_WAIT0();
        __syncthreads();

        // compute: 4 k-steps of 16 channels
#pragma unroll
        for (int ks = 0; ks < 4; ks++) {
            uint32_t ah[2][4], al[2][4];
#pragma unroll
            for (int mi = 0; mi < 2; mi++) {
                uint32_t ao = (uint32_t)((mw * 32 + mi * 16 + arow) * CSTRB + ks * 32 + asel);
                ldsm_x4(ah[mi], sb + SQH + ao);
                ldsm_x4(al[mi], sb + SQL + ao);
            }
#pragma unroll
            for (int ni = 0; ni < 7; ni++) {
                uint32_t bo = (uint32_t)((nw * 56 + ni * 8 + brow) * CSTRB + ks * 32 + bsel);
                uint32_t bh[2], bl[2];
                ldsm_x2(bh, sb + SKH + bo);
                ldsm_x2(bl, sb + SKL + bo);
#pragma unroll
                for (int mi = 0; mi < 2; mi++) {
                    mma16816(acc[mi][ni], ah[mi], bh);   // hh
                    mma16816(acc[mi][ni], al[mi], bh);   // lh
                    mma16816(acc[mi][ni], ah[mi], bl);   // hl
                }
            }
        }
        __syncthreads();   // before next half's fills overwrite the tiles
    }

    // ---- S store to smem (fp32), reusing K' region ----
    float* S = (float*)(sm + SS_OFF);
#pragma unroll
    for (int mi = 0; mi < 2; mi++)
#pragma unroll
        for (int ni = 0; ni < 7; ni++) {
            int m = mw * 32 + mi * 16 + (lid >> 2);
            int n = nw * 56 + ni * 8 + (lid & 3) * 2;
            *(float2*)&S[m * SSTR + n]       = make_float2(acc[mi][ni][0], acc[mi][ni][1]);
            *(float2*)&S[(m + 8) * SSTR + n] = make_float2(acc[mi][ni][2], acc[mi][ni][3]);
        }
    __syncthreads();

    // ---- gather + write out [B][H][W][7][7] ----
    for (int i = tid; i < 64 * NOFF; i += 256) {
        int px = i / NOFF, o = i - px * NOFF;
        int oy = o / KWIN, ox = o - oy * KWIN;
        int py = px >> 3, pxx = px & 7;
        int n = (py + oy) * HALO + (pxx + ox);
        float v = S[px * SSTR + n] + S[px * SSTR + 196 + oy] + S[px * SSTR + 203 + ox];
        size_t gp = (size_t)bb * HWSZ + (th0 + py) * WWID + (tw0 + pxx);
        out[gp * NOFF + o] = v;
    }
}

// ---------------------------------------------------------------------------
extern "C" void kernel_launch(void* const* d_in, const int* in_sizes, int n_in,
                              void* d_out, int out_size)
{
    const float* x     = (const float*)d_in[0];
    const float* w_q   = (const float*)d_in[1];
    const float* w_k   = (const float*)d_in[2];
    const float* rel_h = (const float*)d_in[3];
    const float* rel_w = (const float*)d_in[4];
    float* out = (float*)d_out;

    cudaFuncSetAttribute(qk_gemm_mma, cudaFuncAttributeMaxDynamicSharedMemorySize, G_SMEM);
    cudaFuncSetAttribute(sim_mma,     cudaFuncAttributeMaxDynamicSharedMemorySize, SIM_SMEM);

    wsplit_kernel<<<64, 256>>>(w_q, w_k);
    qk_gemm_mma<<<NPIX / 128, 512, G_SMEM>>>(x);

    dim3 g2(WWID / TP, HH / TP, BATCH);
    sim_mma<<<g2, 256, SIM_SMEM>>>(rel_h, rel_w, out);
}

// round 7
// speedup vs baseline: 3.2215x; 1.0681x over previous
#include <cuda_runtime.h>
#include <cuda_bf16.h>
#include <cstdint>

// ---------------- problem constants ----------------
#define HH    96
#define WWID  96
#define HWSZ  (HH * WWID)      // 9216
#define BATCH 8
#define CIN   256
#define ACH   128
#define KWIN  7
#define NOFF  (KWIN * KWIN)    // 49
#define NPIX  (BATCH * HWSZ)   // 73728

// q/k scratch as bf16 hi/lo, pixel-major [pixel][128ch]
__device__ __nv_bfloat16 g_qh[(size_t)NPIX * ACH];
__device__ __nv_bfloat16 g_ql[(size_t)NPIX * ACH];
__device__ __nv_bfloat16 g_kh[(size_t)NPIX * ACH];
__device__ __nv_bfloat16 g_kl[(size_t)NPIX * ACH];

// W split into bf16 hi/lo, rows 0-127 = w_q, rows 128-255 = w_k
__device__ __nv_bfloat16 g_wh[256][256];
__device__ __nv_bfloat16 g_wl[256][256];

// ---------------- helpers ----------------
__device__ __forceinline__ uint32_t smem_u32(const void* p) {
    uint32_t a;
    asm("{ .reg .u64 t; cvta.to.shared.u64 t, %1; cvt.u32.u64 %0, t; }"
        : "=r"(a) : "l"(p));
    return a;
}

__device__ __forceinline__ void split4(float4 v, uint2& hi, uint2& lo) {
    __nv_bfloat16 h0 = __float2bfloat16(v.x), h1 = __float2bfloat16(v.y);
    __nv_bfloat16 h2 = __float2bfloat16(v.z), h3 = __float2bfloat16(v.w);
    __nv_bfloat16 l0 = __float2bfloat16(v.x - __bfloat162float(h0));
    __nv_bfloat16 l1 = __float2bfloat16(v.y - __bfloat162float(h1));
    __nv_bfloat16 l2 = __float2bfloat16(v.z - __bfloat162float(h2));
    __nv_bfloat16 l3 = __float2bfloat16(v.w - __bfloat162float(h3));
    hi = make_uint2((uint32_t)__bfloat16_as_ushort(h0) | ((uint32_t)__bfloat16_as_ushort(h1) << 16),
                    (uint32_t)__bfloat16_as_ushort(h2) | ((uint32_t)__bfloat16_as_ushort(h3) << 16));
    lo = make_uint2((uint32_t)__bfloat16_as_ushort(l0) | ((uint32_t)__bfloat16_as_ushort(l1) << 16),
                    (uint32_t)__bfloat16_as_ushort(l2) | ((uint32_t)__bfloat16_as_ushort(l3) << 16));
}

__device__ __forceinline__ void ldsm_x4(uint32_t* r, uint32_t addr) {
    asm volatile("ldmatrix.sync.aligned.m8n8.x4.shared.b16 {%0,%1,%2,%3}, [%4];"
                 : "=r"(r[0]), "=r"(r[1]), "=r"(r[2]), "=r"(r[3]) : "r"(addr));
}
__device__ __forceinline__ void ldsm_x2t(uint32_t* r, uint32_t addr) {
    asm volatile("ldmatrix.sync.aligned.m8n8.x2.trans.shared.b16 {%0,%1}, [%2];"
                 : "=r"(r[0]), "=r"(r[1]) : "r"(addr));
}
__device__ __forceinline__ void ldsm_x2(uint32_t* r, uint32_t addr) {
    asm volatile("ldmatrix.sync.aligned.m8n8.x2.shared.b16 {%0,%1}, [%2];"
                 : "=r"(r[0]), "=r"(r[1]) : "r"(addr));
}
__device__ __forceinline__ void mma16816(float* d, const uint32_t* a, const uint32_t* b) {
    asm volatile(
        "mma.sync.aligned.m16n8k16.row.col.f32.bf16.bf16.f32 "
        "{%0,%1,%2,%3}, {%4,%5,%6,%7}, {%8,%9}, {%0,%1,%2,%3};"
        : "+f"(d[0]), "+f"(d[1]), "+f"(d[2]), "+f"(d[3])
        : "r"(a[0]), "r"(a[1]), "r"(a[2]), "r"(a[3]), "r"(b[0]), "r"(b[1]));
}
__device__ __forceinline__ void cp_async16(uint32_t smem_addr, const void* g) {
    asm volatile("cp.async.cg.shared.global [%0], [%1], 16;" :: "r"(smem_addr), "l"(g));
}
__device__ __forceinline__ void cp_async16z(uint32_t smem_addr, const void* g, int sz) {
    asm volatile("cp.async.cg.shared.global [%0], [%1], 16, %2;"
                 :: "r"(smem_addr), "l"(g), "r"(sz));
}
#define CP_COMMIT() asm volatile("cp.async.commit_group;")
#define CP_WAIT0()  asm volatile("cp.async.wait_group 0;" ::: "memory")

// ---------------------------------------------------------------------------
// Pre-kernel: split W into bf16 hi/lo.
// ---------------------------------------------------------------------------
__global__ void wsplit_kernel(const float* __restrict__ w_q,
                              const float* __restrict__ w_k)
{
    int idx = blockIdx.x * 256 + threadIdx.x;
    int row = idx >> 6;
    int c4  = (idx & 63) * 4;
    const float* src = (row < 128) ? &w_q[row * 256 + c4]
                                   : &w_k[(row - 128) * 256 + c4];
    float4 v = *(const float4*)src;
    uint2 h, l; split4(v, h, l);
    *(uint2*)&g_wh[row][c4] = h;
    *(uint2*)&g_wl[row][c4] = l;
}

// ---------------------------------------------------------------------------
// GEMM: D[256 m][128 px] = W_split * X via bf16 HMMA.  (unchanged — at floor)
// ---------------------------------------------------------------------------
#define ASTR_B  144
#define BSTR_B  272
#define A_BYTES 36864
#define B_BYTES 17408
#define ABUF    73728
#define BBUF    34816
#define BBASE   147456
#define G_SMEM  217088
#define EPSTR   136

__global__ __launch_bounds__(512, 1) void qk_gemm_mma(const float* __restrict__ x)
{
    extern __shared__ char gsm[];
    const uint32_t sb = smem_u32(gsm);
    const int tid = threadIdx.x;
    const int wid = tid >> 5;
    const int lid = tid & 31;
    const int mw  = wid & 3;
    const int nw  = wid >> 2;

    const int n0  = blockIdx.x * 128;
    const int b   = n0 / HWSZ;
    const int hw0 = n0 % HWSZ;
    const float* __restrict__ xb = x + (size_t)b * CIN * HWSZ + hw0;

    float acc[4][4][4];
#pragma unroll
    for (int mi = 0; mi < 4; mi++)
#pragma unroll
        for (int ni = 0; ni < 4; ni++)
#pragma unroll
            for (int c = 0; c < 4; c++) acc[mi][ni][c] = 0.0f;

    auto loadW = [&](int chunk, int buf) {
        int c0 = chunk * 64;
#pragma unroll
        for (int j = 0; j < 8; j++) {
            int pc  = tid + j * 512;
            int sp  = pc >> 11;
            int rem = pc & 2047;
            int row = rem >> 3;
            int kp  = rem & 7;
            const __nv_bfloat16* wsrc = sp ? &g_wl[row][c0 + kp * 8]
                                           : &g_wh[row][c0 + kp * 8];
            cp_async16(sb + buf * ABUF + sp * A_BYTES + row * ASTR_B + kp * 16, wsrc);
        }
        CP_COMMIT();
    };
    auto ldgX = [&](int chunk, float4* xr) {
        int c0 = chunk * 64;
#pragma unroll
        for (int j = 0; j < 4; j++) {
            int idx = tid + j * 512;
            int ch  = idx >> 5;
            int p4  = (idx & 31) * 4;
            xr[j] = *(const float4*)&xb[(size_t)(c0 + ch) * HWSZ + p4];
        }
    };
    auto stsX = [&](const float4* xr, int buf) {
        char* bbase = gsm + BBASE + buf * BBUF;
#pragma unroll
        for (int j = 0; j < 4; j++) {
            int idx = tid + j * 512;
            int ch  = idx >> 5;
            int p4  = (idx & 31) * 4;
            uint2 hv, lv; split4(xr[j], hv, lv);
            int off = ch * BSTR_B + p4 * 2;
            *(uint2*)(bbase + off)           = hv;
            *(uint2*)(bbase + B_BYTES + off) = lv;
        }
    };

    float4 xr[4];
    loadW(0, 0);
    ldgX(0, xr);
    stsX(xr, 0);
    CP_WAIT0();
    __syncthreads();

    const int arow = (lid & 15);
    const int acol = (lid >> 4) * 16;

    for (int chunk = 0; chunk < 4; chunk++) {
        const int cur = chunk & 1;
        if (chunk < 3) {
            loadW(chunk + 1, cur ^ 1);
            ldgX(chunk + 1, xr);
        }
        const uint32_t ahb = sb + cur * ABUF;
        const uint32_t alb = ahb + A_BYTES;
        const uint32_t bhb = sb + BBASE + cur * BBUF;
        const uint32_t blb = bhb + B_BYTES;
#pragma unroll
        for (int ks = 0; ks < 4; ks++) {
            uint32_t ah[4][4], al[4][4];
#pragma unroll
            for (int mi = 0; mi < 4; mi++) {
                uint32_t off = (uint32_t)((mw * 64 + mi * 16 + arow) * ASTR_B + ks * 32 + acol);
                ldsm_x4(ah[mi], ahb + off);
                ldsm_x4(al[mi], alb + off);
            }
#pragma unroll
            for (int ni = 0; ni < 4; ni++) {
                uint32_t boff = (uint32_t)((ks * 16 + (lid & 15)) * BSTR_B +
                                           (nw * 32 + ni * 8) * 2);
                uint32_t bh[2], bl[2];
                ldsm_x2t(bh, bhb + boff);
                ldsm_x2t(bl, blb + boff);
#pragma unroll
                for (int mi = 0; mi < 4; mi++) {
                    mma16816(acc[mi][ni], ah[mi], bh);
                    mma16816(acc[mi][ni], al[mi], bh);
                    mma16816(acc[mi][ni], ah[mi], bl);
                }
            }
        }
        if (chunk < 3) {
            stsX(xr, cur ^ 1);
            CP_WAIT0();
        }
        __syncthreads();
    }

    float* ep = (float*)gsm;
#pragma unroll
    for (int phase = 0; phase < 2; phase++) {
        if ((mw >> 1) == phase) {
            int chb = (mw & 1) * 64 + (lid >> 2);
            int pxb = nw * 32 + (lid & 3) * 2;
#pragma unroll
            for (int mi = 0; mi < 4; mi++)
#pragma unroll
                for (int ni = 0; ni < 4; ni++) {
                    int ch = chb + mi * 16;
                    int px = pxb + ni * 8;
                    *(float2*)&ep[ch * EPSTR + px]       = make_float2(acc[mi][ni][0], acc[mi][ni][1]);
                    *(float2*)&ep[(ch + 8) * EPSTR + px] = make_float2(acc[mi][ni][2], acc[mi][ni][3]);
                }
        }
        __syncthreads();
        __nv_bfloat16* __restrict__ oh = phase ? g_kh : g_qh;
        __nv_bfloat16* __restrict__ ol = phase ? g_kl : g_ql;
#pragma unroll
        for (int j = 0; j < 4; j++) {
            int i  = tid + j * 512;
            int px = i & 127;
            int c8 = (i >> 7) * 8;
            uint32_t hp[4], lp[4];
#pragma unroll
            for (int t = 0; t < 4; t++) {
                float f0 = ep[(c8 + 2 * t) * EPSTR + px];
                float f1 = ep[(c8 + 2 * t + 1) * EPSTR + px];
                __nv_bfloat16 h0 = __float2bfloat16(f0), h1 = __float2bfloat16(f1);
                __nv_bfloat16 l0 = __float2bfloat16(f0 - __bfloat162float(h0));
                __nv_bfloat16 l1 = __float2bfloat16(f1 - __bfloat162float(h1));
                hp[t] = (uint32_t)__bfloat16_as_ushort(h0) | ((uint32_t)__bfloat16_as_ushort(h1) << 16);
                lp[t] = (uint32_t)__bfloat16_as_ushort(l0) | ((uint32_t)__bfloat16_as_ushort(l1) << 16);
            }
            size_t base = (size_t)(n0 + px) * ACH + c8;
            *(uint4*)&oh[base] = make_uint4(hp[0], hp[1], hp[2], hp[3]);
            *(uint4*)&ol[base] = make_uint4(lp[0], lp[1], lp[2], lp[3]);
        }
        __syncthreads();
    }
}

// ---------------------------------------------------------------------------
// Kernel 2: sim via row-pair blocked tensor GEMMs.
// Per 8x8 tile: 4 blocks; block b = pixel rows {2b, 2b+1} (M=16 pixels).
// B for block b = halo rows 28b..28b+111 (8 halo rows x 14) + bias rows.
// S_block[16][128]: cols 0..111 halo, 112..118 rel_h(oy), 120..126 rel_w(ox).
// Channel-split into 2 halves of 64 ch accumulating into the same registers;
// rel_h lives in half 0 (ch 0..63), rel_w in half 1 (ch 64..127).
// Halo smem rows: 0..195 = 14x14 halo, 196..202 rel_h, 203 zero,
//                 204..210 rel_w, 211 zero.
// 8 warps = 4 blocks x 2 N-halves (64 cols each).
// ---------------------------------------------------------------------------
#define TP     8
#define HALO   14
#define CSTRB  144                       // 64 bf16 (128 B) + 16 pad
#define SQH    0
#define SQL    9216                      // 64*144
#define SKH    18432
#define SKL    48960                     // SKH + 212*144
#define SIM_SMEM 79488                   // SKL + 212*144
#define SS_OFF 18432                     // S (fp32) reuses K region
#define SSTR2  132                       // S floats per row (128 + 4 pad)

__global__ __launch_bounds__(256, 2) void sim_mma(
    const float* __restrict__ rel_h,
    const float* __restrict__ rel_w,
    float* __restrict__ out)
{
    extern __shared__ char sm[];
    const uint32_t sb = smem_u32(sm);
    const int tid = threadIdx.x;
    const int wid = tid >> 5;
    const int lid = tid & 31;
    const int bb  = blockIdx.z;
    const int th0 = blockIdx.y * TP;
    const int tw0 = blockIdx.x * TP;

    const int blk = wid >> 1;     // 0..3 : pixel-row pair
    const int nh  = wid & 1;      // 0..1 : N half (cols 0..63 / 64..127)

    float acc[8][4];
#pragma unroll
    for (int ni = 0; ni < 8; ni++)
#pragma unroll
        for (int c = 0; c < 4; c++) acc[ni][c] = 0.0f;

    const int arow = lid & 15;
    const int asel = (lid >> 4) * 16;
    const int brow = lid & 7;
    const int bsel = ((lid >> 3) & 1) * 16;

    for (int half = 0; half < 2; half++) {
        const int ch0 = half * 64;

        // Q fill: 2 splits x 64 rows x 8 uint4
        for (int i = tid; i < 1024; i += 256) {
            int s = i >> 9, rem = i & 511, r = rem >> 3, c16 = rem & 7;
            int py = r >> 3, pxx = r & 7;
            size_t gp = (size_t)bb * HWSZ + (th0 + py) * WWID + (tw0 + pxx);
            const __nv_bfloat16* src = (s ? g_ql : g_qh) + gp * ACH + ch0 + c16 * 8;
            cp_async16(sb + (s ? SQL : SQH) + r * CSTRB + c16 * 16, src);
        }
        // K halo fill (zero-fill OOB): rows 0..195
        for (int i = tid; i < 3136; i += 256) {
            int s = (i >= 1568) ? 1 : 0;
            int rem = i - s * 1568;
            int hp = rem >> 3, c16 = rem & 7;
            int hy = hp / HALO, hx = hp - hy * HALO;
            int gh = th0 + hy - 3, gw = tw0 + hx - 3;
            bool ok = ((unsigned)gh < HH) && ((unsigned)gw < WWID);
            size_t gp = ok ? ((size_t)bb * HWSZ + gh * WWID + gw) : 0;
            const __nv_bfloat16* src = (s ? g_kl : g_kh) + gp * ACH + ch0 + c16 * 8;
            cp_async16z(sb + (s ? SKL : SKH) + hp * CSTRB + c16 * 16, src, ok ? 16 : 0);
        }
        CP_COMMIT();

        // bias rows 196..211 (16 rows x 64 ch x 2 splits)
        // half 0: rows 196..202 = rel_h, rest 0.  half 1: rows 204..210 = rel_w, rest 0.
        for (int i = tid; i < 2048; i += 256) {
            int s = (i >= 1024) ? 1 : 0;
            int rem = i - s * 1024;
            int rl = rem >> 6, ch = rem & 63;
            float v = 0.0f;
            if (half == 0) { if (rl < 7) v = rel_h[ch * 7 + rl]; }
            else           { if (rl >= 8 && rl < 15) v = rel_w[ch * 7 + (rl - 8)]; }
            __nv_bfloat16 h = __float2bfloat16(v);
            __nv_bfloat16 o16 = s ? __float2bfloat16(v - __bfloat162float(h)) : h;
            *(__nv_bfloat16*)(sm + (s ? SKL : SKH) + (196 + rl) * CSTRB + ch * 2) = o16;
        }
        CP_WAIT0();
        __syncthreads();

        // compute: 4 k-steps of 16 channels
#pragma unroll
        for (int ks = 0; ks < 4; ks++) {
            uint32_t ah[4], al[4];
            uint32_t ao = (uint32_t)((blk * 16 + arow) * CSTRB + ks * 32 + asel);
            ldsm_x4(ah, sb + SQH + ao);
            ldsm_x4(al, sb + SQL + ao);
#pragma unroll
            for (int ni = 0; ni < 8; ni++) {
                int niG = nh * 8 + ni;
                int rbase = (niG < 14) ? (blk * 28 + niG * 8) : (196 + (niG - 14) * 8);
                uint32_t bo = (uint32_t)((rbase + brow) * CSTRB + ks * 32 + bsel);
                uint32_t bh[2], bl[2];
                ldsm_x2(bh, sb + SKH + bo);
                ldsm_x2(bl, sb + SKL + bo);
                mma16816(acc[ni], ah, bh);   // hh
                mma16816(acc[ni], al, bh);   // lh
                mma16816(acc[ni], ah, bl);   // hl
            }
        }
        __syncthreads();   // before next half's fills overwrite the tiles
    }

    // ---- S store to smem (fp32), reusing K region ----
    float* S = (float*)(sm + SS_OFF);
    {
        float* Sb = S + blk * 16 * SSTR2;
        int m = lid >> 2;
        int n = nh * 64 + (lid & 3) * 2;
#pragma unroll
        for (int ni = 0; ni < 8; ni++) {
            *(float2*)&Sb[m * SSTR2 + n + ni * 8]       = make_float2(acc[ni][0], acc[ni][1]);
            *(float2*)&Sb[(m + 8) * SSTR2 + n + ni * 8] = make_float2(acc[ni][2], acc[ni][3]);
        }
    }
    __syncthreads();

    // ---- gather + write out [B][H][W][7][7] ----
    for (int i = tid; i < 64 * NOFF; i += 256) {
        int px = i / NOFF, o = i - px * NOFF;
        int oy = o / KWIN, ox = o - oy * KWIN;
        int py = px >> 3, pxx = px & 7;
        int b  = py >> 1, r = py & 1;
        const float* Sb = S + (b * 16 + r * 8 + pxx) * SSTR2;
        float v = Sb[(oy + r) * HALO + pxx + ox] + Sb[112 + oy] + Sb[120 + ox];
        size_t gp = (size_t)bb * HWSZ + (th0 + py) * WWID + (tw0 + pxx);
        out[gp * NOFF + o] = v;
    }
}

// ---------------------------------------------------------------------------
extern "C" void kernel_launch(void* const* d_in, const int* in_sizes, int n_in,
                              void* d_out, int out_size)
{
    const float* x     = (const float*)d_in[0];
    const float* w_q   = (const float*)d_in[1];
    const float* w_k   = (const float*)d_in[2];
    const float* rel_h = (const float*)d_in[3];
    const float* rel_w = (const float*)d_in[4];
    float* out = (float*)d_out;

    cudaFuncSetAttribute(qk_gemm_mma, cudaFuncAttributeMaxDynamicSharedMemorySize, G_SMEM);
    cudaFuncSetAttribute(sim_mma,     cudaFuncAttributeMaxDynamicSharedMemorySize, SIM_SMEM);

    wsplit_kernel<<<64, 256>>>(w_q, w_k);
    qk_gemm_mma<<<NPIX / 128, 512, G_SMEM>>>(x);

    dim3 g2(WWID / TP, HH / TP, BATCH);
    sim_mma<<<g2, 256, SIM_SMEM>>>(rel_h, rel_w, out);
}